// round 2
// baseline (speedup 1.0000x reference)
#include <cuda_runtime.h>
#include <math.h>

#define TT 20
#define CC 128
#define DM 256
#define NH 16
#define HWP 16384          // H*W
#define ZROW 132           // padded row stride (C=128 + 4)
#define SSTRIDE 2644       // per-sample z stride
#define ASTRIDE 2112       // A per-sample stride = 16*132

// smem layout offsets (floats)
#define OFF_Z   0
#define OFF_RS  21152      // 8*SSTRIDE
#define OFF_SC  23264      // +16*132   (COLS overlays here pre-phase2)
#define OFF_AT  25824      // +8*320
#define OFF_PL  28384      // +8*320
#define OFF_H1  30432      // +8*256
#define OFF_OB  31456      // +8*128
#define OFF_GS  32608      // +128*9
#define OFF_CR  32864      // +8*16*2
#define SMEM_FLOATS 32992  // +8*16
#define SMEM_BYTES (SMEM_FLOATS * 4)

__device__ float g_qk[NH * DM];
__device__ float g_R[NH * CC];       // raw R
__device__ float g_Rp[NH * CC];      // in_w-weighted R
__device__ float g_G[NH * NH];       // per-group sums of Rp
__device__ float g_bR[NH];
__device__ float g_Wp[DM * CC];      // in_w-weighted inconv_w
__device__ float g_GW[DM * NH];      // per-group sums of Wp
__device__ float g_bW[DM];
__device__ float g_vconst[2 * TT * DM];
__device__ float g_sconst[2 * TT * NH];

union F2U { float2 f; unsigned long long u; };

__device__ __forceinline__ float2 fma2(float2 a, float2 b, float2 c) {
    F2U ua, ub, uc, ud;
    ua.f = a; ub.f = b; uc.f = c;
    asm("fma.rn.f32x2 %0, %1, %2, %3;"
        : "=l"(ud.u) : "l"(ua.u), "l"(ub.u), "l"(uc.u));
    return ud.f;
}

// ---------------------------------------------------------------------------
__global__ void ltae_setup(const int* __restrict__ bpos,
                           const float* __restrict__ in_w,
                           const float* __restrict__ in_b,
                           const float* __restrict__ inconv_w,
                           const float* __restrict__ inconv_b,
                           const float* __restrict__ Q,
                           const float* __restrict__ k_w,
                           const float* __restrict__ k_b) {
    int tid = threadIdx.x;
    // qk[h][dm] = sum_d Q[h,d] * k_w[h*4+d, dm]
    for (int i = tid; i < NH * DM; i += 256) {
        int h = i >> 8, dm = i & 255;
        float acc = 0.f;
        #pragma unroll
        for (int d = 0; d < 4; d++) acc += Q[h * 4 + d] * k_w[(h * 4 + d) * DM + dm];
        g_qk[i] = acc;
    }
    // vconst[b][t][dm] = inconv_b[dm] + pe(b,t,dm)
    for (int i = tid; i < 2 * TT * DM; i += 256) {
        int dm = i & 255; int bt = i >> 8;
        int ii = dm & 15;
        double ex = (double)(2 * (ii / 2)) / 16.0;
        float denom = (float)pow(1000.0, ex);
        float tab = (float)bpos[bt] / denom;
        float pe = (ii & 1) ? cosf(tab) : sinf(tab);
        g_vconst[i] = inconv_b[dm] + pe;
    }
    __syncthreads();
    // R[h][c] = sum_dm qk[h,dm] * inconv_w[dm,c]
    for (int i = tid; i < NH * CC; i += 256) {
        int h = i >> 7, c = i & 127;
        float acc = 0.f;
        for (int dm = 0; dm < DM; dm++) acc += g_qk[h * DM + dm] * inconv_w[dm * CC + c];
        g_R[i] = acc;
    }
    // sconst[b][t][h]
    for (int i = tid; i < 2 * TT * NH; i += 256) {
        int h = i & 15; int bt = i >> 4;
        float acc = 0.f;
        #pragma unroll
        for (int d = 0; d < 4; d++) acc += Q[h * 4 + d] * k_b[h * 4 + d];
        for (int dm = 0; dm < DM; dm++) acc += g_vconst[bt * DM + dm] * g_qk[h * DM + dm];
        g_sconst[i] = acc;
    }
    __syncthreads();
    // Rp, bR, G
    for (int i = tid; i < NH * CC; i += 256) {
        int c = i & 127;
        g_Rp[i] = in_w[c] * g_R[i];
    }
    for (int i = tid; i < NH; i += 256) {
        float acc = 0.f;
        for (int c = 0; c < CC; c++) acc += in_b[c] * g_R[i * CC + c];
        g_bR[i] = acc;
    }
    // Wp, bW, GW (GW directly from in_w*inconv_w)
    for (int i = tid; i < DM * CC; i += 256) {
        int c = i & 127;
        g_Wp[i] = in_w[c] * inconv_w[i];
    }
    for (int i = tid; i < DM; i += 256) {
        float acc = 0.f;
        for (int c = 0; c < CC; c++) acc += in_b[c] * inconv_w[i * CC + c];
        g_bW[i] = acc;
    }
    __syncthreads();
    for (int i = tid; i < NH * NH; i += 256) {
        int h = i >> 4, g = i & 15;
        float acc = 0.f;
        #pragma unroll
        for (int j = 0; j < 8; j++) acc += g_Rp[h * CC + g * 8 + j];
        g_G[i] = acc;
    }
    for (int i = tid; i < DM * NH; i += 256) {
        int d = i >> 4, g = i & 15;
        float acc = 0.f;
        #pragma unroll
        for (int j = 0; j < 8; j++) acc += g_Wp[d * CC + g * 8 + j];
        g_GW[i] = acc;
    }
}

// ---------------------------------------------------------------------------
__global__ void __launch_bounds__(512, 1)
ltae_main(const float* __restrict__ x,
          const float* __restrict__ mlp_w, const float* __restrict__ mlp_b,
          const float* __restrict__ ln_w, const float* __restrict__ ln_b,
          const float* __restrict__ on_w, const float* __restrict__ on_b,
          float* __restrict__ out) {
    extern __shared__ float sm[];
    float* Z  = sm + OFF_Z;
    float* RS = sm + OFF_RS;
    float* SC = sm + OFF_SC;
    float* COLS = sm + OFF_SC;     // overlay: consumed before SC is written
    float* AT = sm + OFF_AT;
    float* PL = sm + OFF_PL;
    float* H1 = sm + OFF_H1;
    float* OB = sm + OFF_OB;
    float* GS = sm + OFF_GS;       // per (s,g): [0]=inv, [1]=mu*inv
    float* CR = sm + OFF_CR;       // per (s,h) score correction

    const int tid = threadIdx.x;
    const int blk = blockIdx.x;
    const int wblk = blk & 15;
    const int hrow = (blk >> 4) & 127;
    const int b = blk >> 11;
    const int w0 = wblk * 8;

    const float* xb = x + (size_t)b * TT * CC * HWP + (size_t)hrow * 128 + w0;

    // stage Rp into smem
    for (int i = tid; i < NH * CC; i += 512) {
        int h = i >> 7, c = i & 127;
        RS[h * ZROW + c] = g_Rp[i];
    }

    // ---- Phase 1: gather into regs, column partials, stats, scaled write
    const int s = tid & 7;
    const int lane64 = tid >> 3;
    float v[40];
    #pragma unroll
    for (int k = 0; k < 40; k++) {
        int pair = lane64 + (k << 6);       // = t*128 + c ; c = lane64 or lane64+64
        v[k] = xb[(size_t)pair * HWP + s];
    }
    {
        float s0 = 0.f, q0 = 0.f, s1 = 0.f, q1 = 0.f;
        #pragma unroll
        for (int t = 0; t < TT; t++) {
            float a = v[2 * t], bq = v[2 * t + 1];
            s0 += a; q0 += a * a;
            s1 += bq; q1 += bq * bq;
        }
        float2 p0; p0.x = s0; p0.y = q0;
        float2 p1; p1.x = s1; p1.y = q1;
        *(float2*)&COLS[s * 260 + lane64 * 2] = p0;
        *(float2*)&COLS[s * 260 + (lane64 + 64) * 2] = p1;
    }
    __syncthreads();

    if (tid < 128) {
        int ss = tid >> 4, g = tid & 15;
        float sum = 0.f, sq = 0.f;
        #pragma unroll
        for (int j = 0; j < 8; j++) {
            float2 p = *(const float2*)&COLS[ss * 260 + (g * 8 + j) * 2];
            sum += p.x; sq += p.y;
        }
        float mu = sum * (1.f / 160.f);
        float var = sq * (1.f / 160.f) - mu * mu;
        float inv = rsqrtf(var + 1e-5f);
        GS[(ss * 16 + g) * 2]     = inv;
        GS[(ss * 16 + g) * 2 + 1] = mu * inv;
    }
    __syncthreads();

    // CORR per (s,h)
    if (tid < 128) {
        int ss = tid >> 4, h = tid & 15;
        float c = g_bR[h];
        #pragma unroll
        for (int g = 0; g < 16; g++)
            c -= GS[(ss * 16 + g) * 2 + 1] * g_G[h * 16 + g];
        CR[ss * 16 + h] = c;
    }
    // scaled Z write (Zs = raw * inv_g)
    {
        float inv0 = GS[(s * 16 + (lane64 >> 3)) * 2];
        float inv1 = GS[(s * 16 + 8 + (lane64 >> 3)) * 2];
        float* zp = Z + s * SSTRIDE;
        #pragma unroll
        for (int k = 0; k < 40; k++) {
            int pair = lane64 + (k << 6);
            int t = pair >> 7, c = pair & 127;
            zp[t * ZROW + c] = v[k] * ((k & 1) ? inv1 : inv0);
        }
    }
    __syncthreads();

    // ---- Phase 2: scores (2t x 4h register tiles, packed f32x2)
    if (tid < 320) {
        int hq = tid & 3;
        int tmp = tid >> 2;
        int tq = tmp % 10;
        int ss = tmp / 10;
        int t0 = tq * 2;
        const float4* z0 = (const float4*)(Z + ss * SSTRIDE + t0 * ZROW);
        const float4* z1 = (const float4*)(Z + ss * SSTRIDE + (t0 + 1) * ZROW);
        float2 acc[2][4];
        #pragma unroll
        for (int tt = 0; tt < 2; tt++)
            #pragma unroll
            for (int j = 0; j < 4; j++) { acc[tt][j].x = 0.f; acc[tt][j].y = 0.f; }
        #pragma unroll 8
        for (int c4 = 0; c4 < 32; c4++) {
            float4 a0 = z0[c4], a1 = z1[c4];
            float2 a0l, a0h, a1l, a1h;
            a0l.x = a0.x; a0l.y = a0.y; a0h.x = a0.z; a0h.y = a0.w;
            a1l.x = a1.x; a1l.y = a1.y; a1h.x = a1.z; a1h.y = a1.w;
            #pragma unroll
            for (int j = 0; j < 4; j++) {
                float4 r = *(const float4*)(RS + (hq * 4 + j) * ZROW + c4 * 4);
                float2 rl, rh;
                rl.x = r.x; rl.y = r.y; rh.x = r.z; rh.y = r.w;
                acc[0][j] = fma2(a0l, rl, acc[0][j]);
                acc[0][j] = fma2(a0h, rh, acc[0][j]);
                acc[1][j] = fma2(a1l, rl, acc[1][j]);
                acc[1][j] = fma2(a1h, rh, acc[1][j]);
            }
        }
        #pragma unroll
        for (int tt = 0; tt < 2; tt++)
            #pragma unroll
            for (int j = 0; j < 4; j++) {
                int h = hq * 4 + j, t = t0 + tt;
                SC[ss * 320 + h * 20 + t] =
                    (acc[tt][j].x + acc[tt][j].y + CR[ss * 16 + h]
                     + g_sconst[(b * TT + t) * NH + h]) * 0.5f;
            }
    }
    __syncthreads();

    // ---- Phase 3: softmax, transposed attn [s][t][h]
    if (tid < 128) {
        int ss = tid >> 4, h = tid & 15;
        const float* sp = SC + ss * 320 + h * 20;
        float m = -1e30f;
        #pragma unroll
        for (int t = 0; t < TT; t++) m = fmaxf(m, sp[t]);
        float e[TT]; float sumv = 0.f;
        #pragma unroll
        for (int t = 0; t < TT; t++) { e[t] = expf(sp[t] - m); sumv += e[t]; }
        float r = 1.f / sumv;
        #pragma unroll
        for (int t = 0; t < TT; t++) AT[ss * 320 + t * 16 + h] = e[t] * r;
    }
    __syncthreads();

    // ---- Phase 4: A[s,h,c] = sum_t attn * Zs  (head-paired f32x2)
    {
        int ss4 = tid >> 6;
        int cl = tid & 63;
        float2 acc[8][2];
        #pragma unroll
        for (int hp = 0; hp < 8; hp++) {
            acc[hp][0].x = 0.f; acc[hp][0].y = 0.f;
            acc[hp][1].x = 0.f; acc[hp][1].y = 0.f;
        }
        const float* zp = Z + ss4 * SSTRIDE + cl * 2;
        const float* ap = AT + ss4 * 320;
        #pragma unroll 4
        for (int t = 0; t < TT; t++) {
            float2 zz = *(const float2*)(zp + t * ZROW);
            float2 zx, zy;
            zx.x = zz.x; zx.y = zz.x;
            zy.x = zz.y; zy.y = zz.y;
            const float2* aq = (const float2*)(ap + t * 16);
            #pragma unroll
            for (int hp = 0; hp < 8; hp++) {
                float2 ah = aq[hp];
                acc[hp][0] = fma2(ah, zx, acc[hp][0]);
                acc[hp][1] = fma2(ah, zy, acc[hp][1]);
            }
        }
        __syncthreads();              // all Z reads complete before overlay
        #pragma unroll
        for (int hp = 0; hp < 8; hp++) {
            float2 we, wo;
            we.x = acc[hp][0].x; we.y = acc[hp][1].x;   // head 2hp,  c pair
            wo.x = acc[hp][0].y; wo.y = acc[hp][1].y;   // head 2hp+1
            *(float2*)(Z + ss4 * ASTRIDE + (2 * hp) * ZROW + cl * 2) = we;
            *(float2*)(Z + ss4 * ASTRIDE + (2 * hp + 1) * ZROW + cl * 2) = wo;
        }
    }
    __syncthreads();

    // ---- Phase 5: pooled (2 d per thread, 4 samples, packed f32x2)
    if (tid < 256) {
        int e = tid & 7, h = (tid >> 3) & 15, sh = tid >> 7;
        int d0 = h * 16 + e, d1 = d0 + 8;
        float2 acc0[4], acc1[4];
        #pragma unroll
        for (int j = 0; j < 4; j++) {
            acc0[j].x = 0.f; acc0[j].y = 0.f;
            acc1[j].x = 0.f; acc1[j].y = 0.f;
        }
        const float4* wr0 = (const float4*)(g_Wp + d0 * CC);
        const float4* wr1 = (const float4*)(g_Wp + d1 * CC);
        #pragma unroll 8
        for (int c4 = 0; c4 < 32; c4++) {
            float4 wa = __ldg(wr0 + c4);
            float4 wb = __ldg(wr1 + c4);
            float2 wal, wah, wbl, wbh;
            wal.x = wa.x; wal.y = wa.y; wah.x = wa.z; wah.y = wa.w;
            wbl.x = wb.x; wbl.y = wb.y; wbh.x = wb.z; wbh.y = wb.w;
            #pragma unroll
            for (int j = 0; j < 4; j++) {
                float4 aq = *(const float4*)(Z + (sh * 4 + j) * ASTRIDE + h * ZROW + c4 * 4);
                float2 al, ah2;
                al.x = aq.x; al.y = aq.y; ah2.x = aq.z; ah2.y = aq.w;
                acc0[j] = fma2(al, wal, acc0[j]);
                acc0[j] = fma2(ah2, wah, acc0[j]);
                acc1[j] = fma2(al, wbl, acc1[j]);
                acc1[j] = fma2(ah2, wbh, acc1[j]);
            }
        }
        float p0[4], p1[4];
        float bw0 = __ldg(g_bW + d0), bw1 = __ldg(g_bW + d1);
        #pragma unroll
        for (int j = 0; j < 4; j++) {
            p0[j] = acc0[j].x + acc0[j].y + bw0;
            p1[j] = acc1[j].x + acc1[j].y + bw1;
        }
        const float* gw0 = g_GW + d0 * 16;
        const float* gw1 = g_GW + d1 * 16;
        #pragma unroll
        for (int g = 0; g < 16; g++) {
            float ga = __ldg(gw0 + g), gb = __ldg(gw1 + g);
            #pragma unroll
            for (int j = 0; j < 4; j++) {
                float m = GS[((sh * 4 + j) * 16 + g) * 2 + 1];
                p0[j] -= m * ga;
                p1[j] -= m * gb;
            }
        }
        const float* vc = g_vconst + b * TT * DM;
        #pragma unroll
        for (int t = 0; t < TT; t++) {
            float va = __ldg(vc + t * DM + d0);
            float vb = __ldg(vc + t * DM + d1);
            #pragma unroll
            for (int j = 0; j < 4; j++) {
                float at = AT[(sh * 4 + j) * 320 + t * 16 + h];
                p0[j] += at * va;
                p1[j] += at * vb;
            }
        }
        #pragma unroll
        for (int j = 0; j < 4; j++) {
            PL[(sh * 4 + j) * 256 + d0] = p0[j];
            PL[(sh * 4 + j) * 256 + d1] = p1[j];
        }
    }
    __syncthreads();

    // ---- Phase 6: MLP (256 threads: (o, sample-half), packed f32x2)
    if (tid < 256) {
        int o = tid & 127, sh = tid >> 7;
        float2 acc[4];
        #pragma unroll
        for (int j = 0; j < 4; j++) { acc[j].x = 0.f; acc[j].y = 0.f; }
        const float4* wr = (const float4*)(mlp_w + o * DM);
        #pragma unroll 8
        for (int d4 = 0; d4 < 64; d4++) {
            float4 wq = __ldg(wr + d4);
            float2 wl, wh;
            wl.x = wq.x; wl.y = wq.y; wh.x = wq.z; wh.y = wq.w;
            #pragma unroll
            for (int j = 0; j < 4; j++) {
                float4 pq = *(const float4*)(PL + (sh * 4 + j) * 256 + d4 * 4);
                float2 pl2, ph2;
                pl2.x = pq.x; pl2.y = pq.y; ph2.x = pq.z; ph2.y = pq.w;
                acc[j] = fma2(pl2, wl, acc[j]);
                acc[j] = fma2(ph2, wh, acc[j]);
            }
        }
        float bo = __ldg(mlp_b + o);
        #pragma unroll
        for (int j = 0; j < 4; j++)
            H1[(sh * 4 + j) * 128 + o] = acc[j].x + acc[j].y + bo;
    }
    __syncthreads();

    // ---- Phase 7: LayerNorm + GELU + GroupNorm + transpose
    if (tid < 256) {
        int ss = tid >> 5, lane = tid & 31;
        float4 vq = *(const float4*)(H1 + ss * 128 + lane * 4);
        float smv = vq.x + vq.y + vq.z + vq.w;
        float sqv = vq.x * vq.x + vq.y * vq.y + vq.z * vq.z + vq.w * vq.w;
        #pragma unroll
        for (int off = 16; off; off >>= 1) {
            smv += __shfl_xor_sync(0xffffffffu, smv, off);
            sqv += __shfl_xor_sync(0xffffffffu, sqv, off);
        }
        float mu = smv * (1.f / 128.f);
        float inv = rsqrtf(sqv * (1.f / 128.f) - mu * mu + 1e-5f);
        float g[4]; float vv[4] = {vq.x, vq.y, vq.z, vq.w};
        #pragma unroll
        for (int j = 0; j < 4; j++) {
            int o = lane * 4 + j;
            float u = (vv[j] - mu) * inv * ln_w[o] + ln_b[o];
            g[j] = 0.5f * u * (1.f + erff(u * 0.70710678118654752f));
        }
        float s4 = g[0] + g[1] + g[2] + g[3];
        float q4 = g[0] * g[0] + g[1] * g[1] + g[2] * g[2] + g[3] * g[3];
        float s8 = s4 + __shfl_xor_sync(0xffffffffu, s4, 1);
        float q8 = q4 + __shfl_xor_sync(0xffffffffu, q4, 1);
        float mu2 = s8 * 0.125f;
        float inv2 = rsqrtf(q8 * 0.125f - mu2 * mu2 + 1e-5f);
        #pragma unroll
        for (int j = 0; j < 4; j++) {
            int o = lane * 4 + j;
            OB[o * 9 + ss] = (g[j] - mu2) * inv2 * on_w[o] + on_b[o];
        }
    }
    __syncthreads();

    // ---- coalesced store
    #pragma unroll
    for (int k = tid; k < 1024; k += 512) {
        int o = k >> 3, sw = k & 7;
        out[(((size_t)(b * 128 + o)) << 14) + hrow * 128 + w0 + sw] = OB[o * 9 + sw];
    }
}

// ---------------------------------------------------------------------------
extern "C" void kernel_launch(void* const* d_in, const int* in_sizes, int n_in,
                              void* d_out, int out_size) {
    const float* x        = (const float*)d_in[0];
    const int*   bpos     = (const int*)  d_in[1];
    const float* in_w     = (const float*)d_in[2];
    const float* in_b     = (const float*)d_in[3];
    const float* inconv_w = (const float*)d_in[4];
    const float* inconv_b = (const float*)d_in[5];
    const float* Q        = (const float*)d_in[6];
    const float* k_w      = (const float*)d_in[7];
    const float* k_b      = (const float*)d_in[8];
    const float* mlp_w    = (const float*)d_in[9];
    const float* mlp_b    = (const float*)d_in[10];
    const float* ln_w     = (const float*)d_in[11];
    const float* ln_b     = (const float*)d_in[12];
    const float* on_w     = (const float*)d_in[13];
    const float* on_b     = (const float*)d_in[14];
    float* out = (float*)d_out;

    cudaFuncSetAttribute(ltae_main, cudaFuncAttributeMaxDynamicSharedMemorySize,
                         SMEM_BYTES);

    ltae_setup<<<1, 256>>>(bpos, in_w, in_b, inconv_w, inconv_b, Q, k_w, k_b);
    ltae_main<<<4096, 512, SMEM_BYTES>>>(x, mlp_w, mlp_b, ln_w, ln_b,
                                         on_w, on_b, out);
}

// round 3
// speedup vs baseline: 2.0317x; 2.0317x over previous
#include <cuda_runtime.h>
#include <math.h>

#define TT 20
#define CC 128
#define DM 256
#define NH 16
#define HWP 16384          // H*W
#define ZROW 132           // padded row stride
#define SSTRIDE 2644       // per-sample z stride
#define ASTRIDE 2112       // A per-sample stride = 16*132

// smem layout offsets (floats)
#define OFF_Z   0
#define OFF_RS  21152      // 8*SSTRIDE
#define OFF_SC  23264      // +16*132 (COLS overlays here pre-phase2)
#define OFF_AT  25824      // +8*320
#define OFF_PL  28384      // +8*320
#define OFF_PH  30432      // +8*256
#define OFF_OB  32480      // +2*8*128
#define OFF_GS  33632      // +128*9
#define OFF_CR  33888      // +8*16*2
#define SMEM_FLOATS 34016  // +8*16
#define SMEM_BYTES (SMEM_FLOATS * 4)

__device__ float g_qk[NH * DM];
__device__ float g_R[NH * CC];
__device__ float g_Rp[NH * CC];      // in_w-weighted R
__device__ float g_G[NH * NH];       // per-group sums of Rp
__device__ float g_bR[NH];
__device__ float g_Wp[DM * CC];      // in_w-weighted inconv_w
__device__ float g_GW[DM * NH];
__device__ float g_GWT[NH * DM];     // transposed: [g][d]
__device__ float g_bW[DM];
__device__ float g_W4[DM * CC];      // [c4][d][j] : coalesced over d
__device__ float g_M4[DM * CC];      // [d4][o][j] : coalesced over o (mlp_w repack)
__device__ float g_vconst[2 * TT * DM];
__device__ float g_sconst[2 * TT * NH];

union F2U { float2 f; unsigned long long u; };

__device__ __forceinline__ float2 fma2(float2 a, float2 b, float2 c) {
    F2U ua, ub, uc, ud;
    ua.f = a; ub.f = b; uc.f = c;
    asm("fma.rn.f32x2 %0, %1, %2, %3;"
        : "=l"(ud.u) : "l"(ua.u), "l"(ub.u), "l"(uc.u));
    return ud.f;
}
__device__ __forceinline__ float2 mk2(float a, float b) {
    float2 r; r.x = a; r.y = b; return r;
}

// ---------------------------------------------------------------------------
__global__ void ltae_setup(const int* __restrict__ bpos,
                           const float* __restrict__ in_w,
                           const float* __restrict__ in_b,
                           const float* __restrict__ inconv_w,
                           const float* __restrict__ inconv_b,
                           const float* __restrict__ Q,
                           const float* __restrict__ k_w,
                           const float* __restrict__ k_b,
                           const float* __restrict__ mlp_w) {
    int tid = threadIdx.x;
    // qk[h][dm]
    for (int i = tid; i < NH * DM; i += 256) {
        int h = i >> 8, dm = i & 255;
        float acc = 0.f;
        #pragma unroll
        for (int d = 0; d < 4; d++) acc += Q[h * 4 + d] * k_w[(h * 4 + d) * DM + dm];
        g_qk[i] = acc;
    }
    // vconst
    for (int i = tid; i < 2 * TT * DM; i += 256) {
        int dm = i & 255; int bt = i >> 8;
        int ii = dm & 15;
        double ex = (double)(2 * (ii / 2)) / 16.0;
        float denom = (float)pow(1000.0, ex);
        float tab = (float)bpos[bt] / denom;
        float pe = (ii & 1) ? cosf(tab) : sinf(tab);
        g_vconst[i] = inconv_b[dm] + pe;
    }
    // M4 repack (no device deps)
    for (int i = tid; i < DM * CC; i += 256) {
        int d4 = i >> 9, rem = i & 511, o = rem >> 2, j = rem & 3;
        g_M4[i] = mlp_w[o * DM + d4 * 4 + j];
    }
    __syncthreads();
    // R[h][c]
    for (int i = tid; i < NH * CC; i += 256) {
        int h = i >> 7, c = i & 127;
        float acc = 0.f;
        for (int dm = 0; dm < DM; dm++) acc += g_qk[h * DM + dm] * inconv_w[dm * CC + c];
        g_R[i] = acc;
    }
    // sconst
    for (int i = tid; i < 2 * TT * NH; i += 256) {
        int h = i & 15; int bt = i >> 4;
        float acc = 0.f;
        #pragma unroll
        for (int d = 0; d < 4; d++) acc += Q[h * 4 + d] * k_b[h * 4 + d];
        for (int dm = 0; dm < DM; dm++) acc += g_vconst[bt * DM + dm] * g_qk[h * DM + dm];
        g_sconst[i] = acc;
    }
    __syncthreads();
    for (int i = tid; i < NH * CC; i += 256) {
        int c = i & 127;
        g_Rp[i] = in_w[c] * g_R[i];
    }
    for (int i = tid; i < NH; i += 256) {
        float acc = 0.f;
        for (int c = 0; c < CC; c++) acc += in_b[c] * g_R[i * CC + c];
        g_bR[i] = acc;
    }
    for (int i = tid; i < DM * CC; i += 256) {
        int c = i & 127;
        g_Wp[i] = in_w[c] * inconv_w[i];
    }
    for (int i = tid; i < DM; i += 256) {
        float acc = 0.f;
        for (int c = 0; c < CC; c++) acc += in_b[c] * inconv_w[i * CC + c];
        g_bW[i] = acc;
    }
    __syncthreads();
    for (int i = tid; i < NH * NH; i += 256) {
        int h = i >> 4, g = i & 15;
        float acc = 0.f;
        #pragma unroll
        for (int j = 0; j < 8; j++) acc += g_Rp[h * CC + g * 8 + j];
        g_G[i] = acc;
    }
    for (int i = tid; i < DM * NH; i += 256) {
        int d = i >> 4, g = i & 15;
        float acc = 0.f;
        #pragma unroll
        for (int j = 0; j < 8; j++) acc += g_Wp[d * CC + g * 8 + j];
        g_GW[i] = acc;
    }
    __syncthreads();
    // W4: [c4][d][j] = Wp[d][4*c4+j]
    for (int i = tid; i < DM * CC; i += 256) {
        int c4 = i >> 10, rem = i & 1023, d = rem >> 2, j = rem & 3;
        g_W4[i] = g_Wp[d * CC + c4 * 4 + j];
    }
    // GWT
    for (int i = tid; i < NH * DM; i += 256) {
        int g = i >> 8, d = i & 255;
        g_GWT[i] = g_GW[d * 16 + g];
    }
}

// ---------------------------------------------------------------------------
__global__ void __launch_bounds__(512, 1)
ltae_main(const float* __restrict__ x,
          const float* __restrict__ mlp_b,
          const float* __restrict__ ln_w, const float* __restrict__ ln_b,
          const float* __restrict__ on_w, const float* __restrict__ on_b,
          float* __restrict__ out) {
    extern __shared__ float sm[];
    float* Z    = sm + OFF_Z;
    float* RS   = sm + OFF_RS;
    float* SC   = sm + OFF_SC;
    float* COLS = sm + OFF_SC;   // overlay, dead before SC written
    float* AT   = sm + OFF_AT;
    float* PL   = sm + OFF_PL;
    float* PH   = sm + OFF_PH;
    float* OB   = sm + OFF_OB;
    float* GS   = sm + OFF_GS;   // per (s,g): [0]=inv, [1]=mu*inv
    float* CR   = sm + OFF_CR;

    const int tid = threadIdx.x;
    const int blk = blockIdx.x;
    const int wblk = blk & 15;
    const int hrow = (blk >> 4) & 127;
    const int b = blk >> 11;
    const int w0 = wblk * 8;

    const float* xb = x + (size_t)b * TT * CC * HWP + (size_t)hrow * 128 + w0;

    // stage Rp into smem
    for (int i = tid; i < NH * CC; i += 512) {
        int h = i >> 7, c = i & 127;
        RS[h * ZROW + c] = g_Rp[i];
    }

    // ---- Phase 1: gather -> smem, inline column partials
    const int s = tid & 7;
    const int lane64 = tid >> 3;
    {
        float s0 = 0.f, q0 = 0.f, s1 = 0.f, q1 = 0.f;
        float* zp = Z + s * SSTRIDE;
        #pragma unroll 4
        for (int k = 0; k < 40; k++) {
            int pair = lane64 + (k << 6);      // t = pair>>7, c = pair&127
            float val = __ldg(xb + (size_t)pair * HWP + s);
            zp[(pair >> 7) * ZROW + (pair & 127)] = val;
            if (k & 1) { s1 += val; q1 += val * val; }
            else       { s0 += val; q0 += val * val; }
        }
        *(float2*)&COLS[s * 260 + lane64 * 2] = mk2(s0, q0);
        *(float2*)&COLS[s * 260 + (lane64 + 64) * 2] = mk2(s1, q1);
    }
    __syncthreads();

    if (tid < 128) {
        int ss = tid >> 4, g = tid & 15;
        float sum = 0.f, sq = 0.f;
        #pragma unroll
        for (int j = 0; j < 8; j++) {
            float2 p = *(const float2*)&COLS[ss * 260 + (g * 8 + j) * 2];
            sum += p.x; sq += p.y;
        }
        float mu = sum * (1.f / 160.f);
        float var = sq * (1.f / 160.f) - mu * mu;
        float inv = rsqrtf(var + 1e-5f);
        GS[(ss * 16 + g) * 2]     = inv;
        GS[(ss * 16 + g) * 2 + 1] = mu * inv;
    }
    __syncthreads();

    // per-(s,h) score correction
    if (tid < 128) {
        int ss = tid >> 4, h = tid & 15;
        float c = g_bR[h];
        #pragma unroll
        for (int g = 0; g < 16; g++)
            c -= GS[(ss * 16 + g) * 2 + 1] * g_G[h * 16 + g];
        CR[ss * 16 + h] = c;
    }
    // in-place scale pass: Zs = raw * inv_g
    {
        float inv0 = GS[(s * 16 + (lane64 >> 3)) * 2];
        float inv1 = GS[(s * 16 + 8 + (lane64 >> 3)) * 2];
        float* zp = Z + s * SSTRIDE;
        #pragma unroll 4
        for (int k = 0; k < 40; k++) {
            int pair = lane64 + (k << 6);
            int idx = (pair >> 7) * ZROW + (pair & 127);
            zp[idx] *= (k & 1) ? inv1 : inv0;
        }
    }
    __syncthreads();

    // ---- Phase 2: scores (2t x 4h tiles, f32x2)
    if (tid < 320) {
        int hq = tid & 3;
        int tmp = tid >> 2;
        int tq = tmp % 10;
        int ss = tmp / 10;
        int t0 = tq * 2;
        const float4* z0 = (const float4*)(Z + ss * SSTRIDE + t0 * ZROW);
        const float4* z1 = (const float4*)(Z + ss * SSTRIDE + (t0 + 1) * ZROW);
        float2 acc[2][4];
        #pragma unroll
        for (int tt = 0; tt < 2; tt++)
            #pragma unroll
            for (int j = 0; j < 4; j++) acc[tt][j] = mk2(0.f, 0.f);
        #pragma unroll 8
        for (int c4 = 0; c4 < 32; c4++) {
            float4 a0 = z0[c4], a1 = z1[c4];
            #pragma unroll
            for (int j = 0; j < 4; j++) {
                float4 r = *(const float4*)(RS + (hq * 4 + j) * ZROW + c4 * 4);
                acc[0][j] = fma2(mk2(a0.x, a0.y), mk2(r.x, r.y), acc[0][j]);
                acc[0][j] = fma2(mk2(a0.z, a0.w), mk2(r.z, r.w), acc[0][j]);
                acc[1][j] = fma2(mk2(a1.x, a1.y), mk2(r.x, r.y), acc[1][j]);
                acc[1][j] = fma2(mk2(a1.z, a1.w), mk2(r.z, r.w), acc[1][j]);
            }
        }
        #pragma unroll
        for (int tt = 0; tt < 2; tt++)
            #pragma unroll
            for (int j = 0; j < 4; j++) {
                int h = hq * 4 + j, t = t0 + tt;
                SC[ss * 320 + h * 20 + t] =
                    (acc[tt][j].x + acc[tt][j].y + CR[ss * 16 + h]
                     + g_sconst[(b * TT + t) * NH + h]) * 0.5f;
            }
    }
    __syncthreads();

    // ---- Phase 3: softmax -> AT [s][t][h]
    if (tid < 128) {
        int ss = tid >> 4, h = tid & 15;
        const float* sp = SC + ss * 320 + h * 20;
        float m = -1e30f;
        #pragma unroll
        for (int t = 0; t < TT; t++) m = fmaxf(m, sp[t]);
        float e[TT]; float sumv = 0.f;
        #pragma unroll
        for (int t = 0; t < TT; t++) { e[t] = expf(sp[t] - m); sumv += e[t]; }
        float r = 1.f / sumv;
        #pragma unroll
        for (int t = 0; t < TT; t++) AT[ss * 320 + t * 16 + h] = e[t] * r;
    }
    __syncthreads();

    // ---- Phase 4: A[s,h,c] = sum_t attn * Zs (head-paired f32x2), overlay
    {
        int ss4 = tid >> 6;
        int cl = tid & 63;
        float2 acc[8][2];
        #pragma unroll
        for (int hp = 0; hp < 8; hp++) {
            acc[hp][0] = mk2(0.f, 0.f);
            acc[hp][1] = mk2(0.f, 0.f);
        }
        const float* zp = Z + ss4 * SSTRIDE + cl * 2;
        const float* ap = AT + ss4 * 320;
        #pragma unroll 4
        for (int t = 0; t < TT; t++) {
            float2 zz = *(const float2*)(zp + t * ZROW);
            float2 zx = mk2(zz.x, zz.x), zy = mk2(zz.y, zz.y);
            const float2* aq = (const float2*)(ap + t * 16);
            #pragma unroll
            for (int hp = 0; hp < 8; hp++) {
                float2 ah = aq[hp];
                acc[hp][0] = fma2(ah, zx, acc[hp][0]);
                acc[hp][1] = fma2(ah, zy, acc[hp][1]);
            }
        }
        __syncthreads();
        #pragma unroll
        for (int hp = 0; hp < 8; hp++) {
            *(float2*)(Z + ss4 * ASTRIDE + (2 * hp) * ZROW + cl * 2)     = mk2(acc[hp][0].x, acc[hp][1].x);
            *(float2*)(Z + ss4 * ASTRIDE + (2 * hp + 1) * ZROW + cl * 2) = mk2(acc[hp][0].y, acc[hp][1].y);
        }
    }
    __syncthreads();

    // ---- Phase 5: pooled; thread owns d (coalesced W4), 8 samples
    if (tid < 256) {
        const int d = tid;
        const int h = d >> 4;
        float2 acc2[8];
        #pragma unroll
        for (int j = 0; j < 8; j++) acc2[j] = mk2(0.f, 0.f);
        #pragma unroll 4
        for (int c4 = 0; c4 < 32; c4++) {
            float4 w = __ldg((const float4*)(g_W4 + c4 * 1024 + d * 4));
            float2 wl = mk2(w.x, w.y), wh = mk2(w.z, w.w);
            #pragma unroll
            for (int j = 0; j < 8; j++) {
                float4 a = *(const float4*)(Z + j * ASTRIDE + h * ZROW + c4 * 4);
                acc2[j] = fma2(mk2(a.x, a.y), wl, acc2[j]);
                acc2[j] = fma2(mk2(a.z, a.w), wh, acc2[j]);
            }
        }
        float p[8];
        float bw = __ldg(g_bW + d);
        #pragma unroll
        for (int j = 0; j < 8; j++) p[j] = acc2[j].x + acc2[j].y + bw;
        #pragma unroll
        for (int g = 0; g < 16; g++) {
            float gw = __ldg(g_GWT + g * 256 + d);
            #pragma unroll
            for (int j = 0; j < 8; j++)
                p[j] -= GS[(j * 16 + g) * 2 + 1] * gw;
        }
        const float* vc = g_vconst + b * TT * DM + d;
        #pragma unroll 4
        for (int t = 0; t < TT; t++) {
            float vv = __ldg(vc + t * DM);
            #pragma unroll
            for (int j = 0; j < 8; j++)
                p[j] += AT[j * 320 + t * 16 + h] * vv;
        }
        #pragma unroll
        for (int j = 0; j < 8; j++) PL[j * 256 + d] = p[j];
    }
    __syncthreads();

    // ---- Phase 6: MLP halves; thread owns o (coalesced M4), dh half of d
    if (tid < 256) {
        const int o = tid & 127;
        const int dh = tid >> 7;
        float2 acc2[8];
        #pragma unroll
        for (int j = 0; j < 8; j++) acc2[j] = mk2(0.f, 0.f);
        const int d4base = dh * 32;
        #pragma unroll 4
        for (int k = 0; k < 32; k++) {
            int d4 = d4base + k;
            float4 w = __ldg((const float4*)(g_M4 + d4 * 512 + o * 4));
            float2 wl = mk2(w.x, w.y), wh = mk2(w.z, w.w);
            #pragma unroll
            for (int j = 0; j < 8; j++) {
                float4 pq = *(const float4*)(PL + j * 256 + d4 * 4);
                acc2[j] = fma2(mk2(pq.x, pq.y), wl, acc2[j]);
                acc2[j] = fma2(mk2(pq.z, pq.w), wh, acc2[j]);
            }
        }
        #pragma unroll
        for (int j = 0; j < 8; j++)
            PH[dh * 1024 + j * 128 + o] = acc2[j].x + acc2[j].y;
    }
    __syncthreads();

    // ---- Phase 7: combine + bias + LN + GELU + GN + transpose
    if (tid < 256) {
        int ss = tid >> 5, lane = tid & 31;
        float4 a0 = *(const float4*)(PH + ss * 128 + lane * 4);
        float4 a1 = *(const float4*)(PH + 1024 + ss * 128 + lane * 4);
        float4 bb = __ldg((const float4*)(mlp_b + lane * 4));
        float4 vq;
        vq.x = a0.x + a1.x + bb.x;
        vq.y = a0.y + a1.y + bb.y;
        vq.z = a0.z + a1.z + bb.z;
        vq.w = a0.w + a1.w + bb.w;
        float smv = vq.x + vq.y + vq.z + vq.w;
        float sqv = vq.x * vq.x + vq.y * vq.y + vq.z * vq.z + vq.w * vq.w;
        #pragma unroll
        for (int off = 16; off; off >>= 1) {
            smv += __shfl_xor_sync(0xffffffffu, smv, off);
            sqv += __shfl_xor_sync(0xffffffffu, sqv, off);
        }
        float mu = smv * (1.f / 128.f);
        float inv = rsqrtf(sqv * (1.f / 128.f) - mu * mu + 1e-5f);
        float g[4]; float vv[4] = {vq.x, vq.y, vq.z, vq.w};
        #pragma unroll
        for (int j = 0; j < 4; j++) {
            int o = lane * 4 + j;
            float u = (vv[j] - mu) * inv * ln_w[o] + ln_b[o];
            g[j] = 0.5f * u * (1.f + erff(u * 0.70710678118654752f));
        }
        float s4 = g[0] + g[1] + g[2] + g[3];
        float q4 = g[0] * g[0] + g[1] * g[1] + g[2] * g[2] + g[3] * g[3];
        float s8 = s4 + __shfl_xor_sync(0xffffffffu, s4, 1);
        float q8 = q4 + __shfl_xor_sync(0xffffffffu, q4, 1);
        float mu2 = s8 * 0.125f;
        float inv2 = rsqrtf(q8 * 0.125f - mu2 * mu2 + 1e-5f);
        #pragma unroll
        for (int j = 0; j < 4; j++) {
            int o = lane * 4 + j;
            OB[o * 9 + ss] = (g[j] - mu2) * inv2 * on_w[o] + on_b[o];
        }
    }
    __syncthreads();

    // ---- coalesced store
    #pragma unroll
    for (int k = tid; k < 1024; k += 512) {
        int o = k >> 3, sw = k & 7;
        out[(((size_t)(b * 128 + o)) << 14) + hrow * 128 + w0 + sw] = OB[o * 9 + sw];
    }
}

// ---------------------------------------------------------------------------
extern "C" void kernel_launch(void* const* d_in, const int* in_sizes, int n_in,
                              void* d_out, int out_size) {
    const float* x        = (const float*)d_in[0];
    const int*   bpos     = (const int*)  d_in[1];
    const float* in_w     = (const float*)d_in[2];
    const float* in_b     = (const float*)d_in[3];
    const float* inconv_w = (const float*)d_in[4];
    const float* inconv_b = (const float*)d_in[5];
    const float* Q        = (const float*)d_in[6];
    const float* k_w      = (const float*)d_in[7];
    const float* k_b      = (const float*)d_in[8];
    const float* mlp_w    = (const float*)d_in[9];
    const float* mlp_b    = (const float*)d_in[10];
    const float* ln_w     = (const float*)d_in[11];
    const float* ln_b     = (const float*)d_in[12];
    const float* on_w     = (const float*)d_in[13];
    const float* on_b     = (const float*)d_in[14];
    float* out = (float*)d_out;

    cudaFuncSetAttribute(ltae_main, cudaFuncAttributeMaxDynamicSharedMemorySize,
                         SMEM_BYTES);

    ltae_setup<<<1, 256>>>(bpos, in_w, in_b, inconv_w, inconv_b, Q, k_w, k_b,
                           mlp_w);
    ltae_main<<<4096, 512, SMEM_BYTES>>>(x, mlp_b, ln_w, ln_b, on_w, on_b, out);
}

// round 4
// speedup vs baseline: 2.4774x; 1.2194x over previous
#include <cuda_runtime.h>
#include <math.h>

#define TT 20
#define CC 128
#define DM 256
#define NH 16
#define HWP 16384
#define ZROW 132
#define SSTRIDE 2644
#define ASTRIDE 2112

// smem offsets (floats) — 4 samples per block
#define OFF_Z   0
#define OFF_RS  10576
#define OFF_SC  12688
#define OFF_AT  13968
#define OFF_PL  15248
#define OFF_PH  16272
#define OFF_OB  17296
#define OFF_GS  17936
#define OFF_CR  18064
#define SMEM_FLOATS 18128
#define SMEM_BYTES (SMEM_FLOATS * 4)

__device__ float g_qk[NH * DM];
__device__ float g_R[NH * CC];
__device__ float g_Rp[NH * CC];
__device__ float g_G[NH * NH];
__device__ float g_bR[NH];
__device__ float g_Wp[DM * CC];
__device__ float g_GW[DM * NH];
__device__ float g_GWT[NH * DM];
__device__ float g_bW[DM];
__device__ float g_W4[DM * CC];      // [c4][d][j]
__device__ float g_M4[DM * CC];      // [d4][o][j]
__device__ float g_vconst[2 * TT * DM];
__device__ float g_sconst[2 * TT * NH];

union F2U { float2 f; unsigned long long u; };

__device__ __forceinline__ float2 fma2(float2 a, float2 b, float2 c) {
    F2U ua, ub, uc, ud;
    ua.f = a; ub.f = b; uc.f = c;
    asm("fma.rn.f32x2 %0, %1, %2, %3;"
        : "=l"(ud.u) : "l"(ua.u), "l"(ub.u), "l"(uc.u));
    return ud.f;
}
__device__ __forceinline__ float2 mk2(float a, float b) {
    float2 r; r.x = a; r.y = b; return r;
}

// ---------------------------------------------------------------------------
// Setup stage A: no inter-dependencies
__global__ void setup_a(const int* __restrict__ bpos,
                        const float* __restrict__ in_w,
                        const float* __restrict__ in_b,
                        const float* __restrict__ inconv_w,
                        const float* __restrict__ inconv_b,
                        const float* __restrict__ Q,
                        const float* __restrict__ k_w,
                        const float* __restrict__ mlp_w) {
    int tid = blockIdx.x * blockDim.x + threadIdx.x;
    int stride = gridDim.x * blockDim.x;
    for (int i = tid; i < NH * DM; i += stride) {
        int h = i >> 8, dm = i & 255;
        float acc = 0.f;
        #pragma unroll
        for (int d = 0; d < 4; d++) acc += Q[h * 4 + d] * k_w[(h * 4 + d) * DM + dm];
        g_qk[i] = acc;
    }
    for (int i = tid; i < 2 * TT * DM; i += stride) {
        int dm = i & 255; int bt = i >> 8;
        int ii = dm & 15;
        double ex = (double)(2 * (ii / 2)) / 16.0;
        float denom = (float)pow(1000.0, ex);
        float tab = (float)bpos[bt] / denom;
        float pe = (ii & 1) ? cosf(tab) : sinf(tab);
        g_vconst[i] = inconv_b[dm] + pe;
    }
    for (int i = tid; i < DM * CC; i += stride) {
        int d4 = i >> 9, rem = i & 511, o = rem >> 2, j = rem & 3;
        g_M4[i] = mlp_w[o * DM + d4 * 4 + j];
    }
    for (int i = tid; i < DM * CC; i += stride) {
        int c = i & 127;
        g_Wp[i] = in_w[c] * inconv_w[i];
    }
    for (int i = tid; i < DM; i += stride) {
        float acc = 0.f;
        for (int c = 0; c < CC; c++) acc += in_b[c] * inconv_w[i * CC + c];
        g_bW[i] = acc;
    }
}

// Setup stage B: depends on qk, vconst, Wp
__global__ void setup_b(const float* __restrict__ inconv_w,
                        const float* __restrict__ Q,
                        const float* __restrict__ k_b) {
    int tid = blockIdx.x * blockDim.x + threadIdx.x;
    int stride = gridDim.x * blockDim.x;
    for (int i = tid; i < NH * CC; i += stride) {
        int h = i >> 7, c = i & 127;
        float acc = 0.f;
        for (int dm = 0; dm < DM; dm++) acc += g_qk[h * DM + dm] * inconv_w[dm * CC + c];
        g_R[i] = acc;
    }
    for (int i = tid; i < 2 * TT * NH; i += stride) {
        int h = i & 15; int bt = i >> 4;
        float acc = 0.f;
        #pragma unroll
        for (int d = 0; d < 4; d++) acc += Q[h * 4 + d] * k_b[h * 4 + d];
        for (int dm = 0; dm < DM; dm++) acc += g_vconst[bt * DM + dm] * g_qk[h * DM + dm];
        g_sconst[i] = acc;
    }
    for (int i = tid; i < DM * NH; i += stride) {
        int d = i >> 4, g = i & 15;
        float acc = 0.f;
        #pragma unroll
        for (int j = 0; j < 8; j++) acc += g_Wp[d * CC + g * 8 + j];
        g_GW[i] = acc;
    }
    for (int i = tid; i < DM * CC; i += stride) {
        int c4 = i >> 10, rem = i & 1023, d = rem >> 2, j = rem & 3;
        g_W4[i] = g_Wp[d * CC + c4 * 4 + j];
    }
}

// Setup stage C: depends on R, GW
__global__ void setup_c(const float* __restrict__ in_w,
                        const float* __restrict__ in_b) {
    int tid = blockIdx.x * blockDim.x + threadIdx.x;
    int stride = gridDim.x * blockDim.x;
    for (int i = tid; i < NH * CC; i += stride) {
        int c = i & 127;
        g_Rp[i] = in_w[c] * g_R[i];
    }
    for (int i = tid; i < NH; i += stride) {
        float acc = 0.f;
        for (int c = 0; c < CC; c++) acc += in_b[c] * g_R[i * CC + c];
        g_bR[i] = acc;
    }
    for (int i = tid; i < NH * NH; i += stride) {
        int h = i >> 4, g = i & 15;
        float acc = 0.f;
        #pragma unroll
        for (int j = 0; j < 8; j++) {
            int c = g * 8 + j;
            acc += in_w[c] * g_R[h * CC + c];
        }
        g_G[i] = acc;
    }
    for (int i = tid; i < NH * DM; i += stride) {
        int g = i >> 8, d = i & 255;
        g_GWT[i] = g_GW[d * 16 + g];
    }
}

// ---------------------------------------------------------------------------
// Main: 256 threads, 4 w positions per block, 3 CTAs/SM target.
__global__ void __launch_bounds__(256, 3)
ltae_main(const float* __restrict__ x,
          const float* __restrict__ mlp_b,
          const float* __restrict__ ln_w, const float* __restrict__ ln_b,
          const float* __restrict__ on_w, const float* __restrict__ on_b,
          float* __restrict__ out) {
    extern __shared__ float sm[];
    float* Z    = sm + OFF_Z;
    float* RS   = sm + OFF_RS;
    float* SC   = sm + OFF_SC;
    float* COLS = sm + OFF_SC;   // overlay, dead before SC is written
    float* AT   = sm + OFF_AT;
    float* PL   = sm + OFF_PL;
    float* PH   = sm + OFF_PH;
    float* OB   = sm + OFF_OB;
    float* GS   = sm + OFF_GS;   // (s,g): [0]=inv, [1]=mu*inv
    float* CR   = sm + OFF_CR;

    const int tid = threadIdx.x;
    const int blk = blockIdx.x;
    const int wblk = blk & 31;
    const int hrow = (blk >> 5) & 127;
    const int b = blk >> 12;
    const int w0 = wblk * 4;

    const float* xb = x + (size_t)b * TT * CC * HWP + (size_t)hrow * 128 + w0;

    // stage Rp
    for (int i = tid; i < NH * CC; i += 256) {
        int h = i >> 7, c = i & 127;
        RS[h * ZROW + c] = g_Rp[i];
    }

    // ---- Phase 1: gather -> smem, inline column partials
    const int s = tid & 3;
    const int lane64 = tid >> 2;
    {
        float s0 = 0.f, q0 = 0.f, s1 = 0.f, q1 = 0.f;
        float* zp = Z + s * SSTRIDE;
        #pragma unroll 4
        for (int k = 0; k < 40; k++) {
            int pair = lane64 + (k << 6);
            float val = __ldg(xb + (size_t)pair * HWP + s);
            zp[(pair >> 7) * ZROW + (pair & 127)] = val;
            if (k & 1) { s1 += val; q1 += val * val; }
            else       { s0 += val; q0 += val * val; }
        }
        *(float2*)&COLS[s * 260 + lane64 * 2] = mk2(s0, q0);
        *(float2*)&COLS[s * 260 + (lane64 + 64) * 2] = mk2(s1, q1);
    }
    __syncthreads();

    if (tid < 64) {
        int ss = tid >> 4, g = tid & 15;
        float sum = 0.f, sq = 0.f;
        #pragma unroll
        for (int j = 0; j < 8; j++) {
            float2 p = *(const float2*)&COLS[ss * 260 + (g * 8 + j) * 2];
            sum += p.x; sq += p.y;
        }
        float mu = sum * (1.f / 160.f);
        float var = sq * (1.f / 160.f) - mu * mu;
        float inv = rsqrtf(var + 1e-5f);
        GS[(ss * 16 + g) * 2]     = inv;
        GS[(ss * 16 + g) * 2 + 1] = mu * inv;
    }
    __syncthreads();

    if (tid < 64) {
        int ss = tid >> 4, h = tid & 15;
        float c = g_bR[h];
        #pragma unroll
        for (int g = 0; g < 16; g++)
            c -= GS[(ss * 16 + g) * 2 + 1] * g_G[h * 16 + g];
        CR[ss * 16 + h] = c;
    }
    // scale pass: Zs = raw * inv_g
    {
        float inv0 = GS[(s * 16 + (lane64 >> 3)) * 2];
        float inv1 = GS[(s * 16 + 8 + (lane64 >> 3)) * 2];
        float* zp = Z + s * SSTRIDE;
        #pragma unroll 4
        for (int k = 0; k < 40; k++) {
            int pair = lane64 + (k << 6);
            int idx = (pair >> 7) * ZROW + (pair & 127);
            zp[idx] *= (k & 1) ? inv1 : inv0;
        }
    }
    __syncthreads();

    // ---- Phase 2: scores (2t x 4h tiles, f32x2), 160 threads
    if (tid < 160) {
        int hq = tid & 3;
        int tmp = tid >> 2;
        int tq = tmp % 10;
        int ss = tmp / 10;
        int t0 = tq * 2;
        const float4* z0 = (const float4*)(Z + ss * SSTRIDE + t0 * ZROW);
        const float4* z1 = (const float4*)(Z + ss * SSTRIDE + (t0 + 1) * ZROW);
        float2 acc[2][4];
        #pragma unroll
        for (int tt = 0; tt < 2; tt++)
            #pragma unroll
            for (int j = 0; j < 4; j++) acc[tt][j] = mk2(0.f, 0.f);
        #pragma unroll 8
        for (int c4 = 0; c4 < 32; c4++) {
            float4 a0 = z0[c4], a1 = z1[c4];
            #pragma unroll
            for (int j = 0; j < 4; j++) {
                float4 r = *(const float4*)(RS + (hq * 4 + j) * ZROW + c4 * 4);
                acc[0][j] = fma2(mk2(a0.x, a0.y), mk2(r.x, r.y), acc[0][j]);
                acc[0][j] = fma2(mk2(a0.z, a0.w), mk2(r.z, r.w), acc[0][j]);
                acc[1][j] = fma2(mk2(a1.x, a1.y), mk2(r.x, r.y), acc[1][j]);
                acc[1][j] = fma2(mk2(a1.z, a1.w), mk2(r.z, r.w), acc[1][j]);
            }
        }
        #pragma unroll
        for (int tt = 0; tt < 2; tt++)
            #pragma unroll
            for (int j = 0; j < 4; j++) {
                int h = hq * 4 + j, t = t0 + tt;
                SC[ss * 320 + h * 20 + t] =
                    (acc[tt][j].x + acc[tt][j].y + CR[ss * 16 + h]
                     + g_sconst[(b * TT + t) * NH + h]) * 0.5f;
            }
    }
    __syncthreads();

    // ---- Phase 3: softmax -> AT [s][t][h]
    if (tid < 64) {
        int ss = tid >> 4, h = tid & 15;
        const float* sp = SC + ss * 320 + h * 20;
        float m = -1e30f;
        #pragma unroll
        for (int t = 0; t < TT; t++) m = fmaxf(m, sp[t]);
        float e[TT]; float sumv = 0.f;
        #pragma unroll
        for (int t = 0; t < TT; t++) { e[t] = expf(sp[t] - m); sumv += e[t]; }
        float r = 1.f / sumv;
        #pragma unroll
        for (int t = 0; t < TT; t++) AT[ss * 320 + t * 16 + h] = e[t] * r;
    }
    __syncthreads();

    // ---- Phase 4: A[s,h,c] overlay (all 256 threads)
    {
        int ss4 = tid >> 6;
        int cl = tid & 63;
        float2 acc[8][2];
        #pragma unroll
        for (int hp = 0; hp < 8; hp++) {
            acc[hp][0] = mk2(0.f, 0.f);
            acc[hp][1] = mk2(0.f, 0.f);
        }
        const float* zp = Z + ss4 * SSTRIDE + cl * 2;
        const float* ap = AT + ss4 * 320;
        #pragma unroll 4
        for (int t = 0; t < TT; t++) {
            float2 zz = *(const float2*)(zp + t * ZROW);
            float2 zx = mk2(zz.x, zz.x), zy = mk2(zz.y, zz.y);
            const float2* aq = (const float2*)(ap + t * 16);
            #pragma unroll
            for (int hp = 0; hp < 8; hp++) {
                float2 ah = aq[hp];
                acc[hp][0] = fma2(ah, zx, acc[hp][0]);
                acc[hp][1] = fma2(ah, zy, acc[hp][1]);
            }
        }
        __syncthreads();
        #pragma unroll
        for (int hp = 0; hp < 8; hp++) {
            *(float2*)(Z + ss4 * ASTRIDE + (2 * hp) * ZROW + cl * 2)     = mk2(acc[hp][0].x, acc[hp][1].x);
            *(float2*)(Z + ss4 * ASTRIDE + (2 * hp + 1) * ZROW + cl * 2) = mk2(acc[hp][0].y, acc[hp][1].y);
        }
    }
    __syncthreads();

    // ---- Phase 5: pooled; thread owns d, 4 samples
    {
        const int d = tid;
        const int h = d >> 4;
        float2 acc2[4];
        #pragma unroll
        for (int j = 0; j < 4; j++) acc2[j] = mk2(0.f, 0.f);
        #pragma unroll 4
        for (int c4 = 0; c4 < 32; c4++) {
            float4 w = __ldg((const float4*)(g_W4 + c4 * 1024 + d * 4));
            float2 wl = mk2(w.x, w.y), wh = mk2(w.z, w.w);
            #pragma unroll
            for (int j = 0; j < 4; j++) {
                float4 a = *(const float4*)(Z + j * ASTRIDE + h * ZROW + c4 * 4);
                acc2[j] = fma2(mk2(a.x, a.y), wl, acc2[j]);
                acc2[j] = fma2(mk2(a.z, a.w), wh, acc2[j]);
            }
        }
        float p[4];
        float bw = __ldg(g_bW + d);
        #pragma unroll
        for (int j = 0; j < 4; j++) p[j] = acc2[j].x + acc2[j].y + bw;
        #pragma unroll
        for (int g = 0; g < 16; g++) {
            float gw = __ldg(g_GWT + g * 256 + d);
            #pragma unroll
            for (int j = 0; j < 4; j++)
                p[j] -= GS[(j * 16 + g) * 2 + 1] * gw;
        }
        const float* vc = g_vconst + b * TT * DM + d;
        #pragma unroll 4
        for (int t = 0; t < TT; t++) {
            float vv = __ldg(vc + t * DM);
            #pragma unroll
            for (int j = 0; j < 4; j++)
                p[j] += AT[j * 320 + t * 16 + h] * vv;
        }
        #pragma unroll
        for (int j = 0; j < 4; j++) PL[j * 256 + d] = p[j];
    }
    __syncthreads();

    // ---- Phase 6: MLP halves; thread owns (o, dh)
    {
        const int o = tid & 127;
        const int dh = tid >> 7;
        float2 acc2[4];
        #pragma unroll
        for (int j = 0; j < 4; j++) acc2[j] = mk2(0.f, 0.f);
        const int d4base = dh * 32;
        #pragma unroll 4
        for (int k = 0; k < 32; k++) {
            int d4 = d4base + k;
            float4 w = __ldg((const float4*)(g_M4 + d4 * 512 + o * 4));
            float2 wl = mk2(w.x, w.y), wh = mk2(w.z, w.w);
            #pragma unroll
            for (int j = 0; j < 4; j++) {
                float4 pq = *(const float4*)(PL + j * 256 + d4 * 4);
                acc2[j] = fma2(mk2(pq.x, pq.y), wl, acc2[j]);
                acc2[j] = fma2(mk2(pq.z, pq.w), wh, acc2[j]);
            }
        }
        #pragma unroll
        for (int j = 0; j < 4; j++)
            PH[dh * 512 + j * 128 + o] = acc2[j].x + acc2[j].y;
    }
    __syncthreads();

    // ---- Phase 7: combine + LN + GELU + GN + transpose (128 threads)
    if (tid < 128) {
        int ss = tid >> 5, lane = tid & 31;
        float4 a0 = *(const float4*)(PH + ss * 128 + lane * 4);
        float4 a1 = *(const float4*)(PH + 512 + ss * 128 + lane * 4);
        float4 bb = __ldg((const float4*)(mlp_b + lane * 4));
        float4 vq;
        vq.x = a0.x + a1.x + bb.x;
        vq.y = a0.y + a1.y + bb.y;
        vq.z = a0.z + a1.z + bb.z;
        vq.w = a0.w + a1.w + bb.w;
        float smv = vq.x + vq.y + vq.z + vq.w;
        float sqv = vq.x * vq.x + vq.y * vq.y + vq.z * vq.z + vq.w * vq.w;
        #pragma unroll
        for (int off = 16; off; off >>= 1) {
            smv += __shfl_xor_sync(0xffffffffu, smv, off);
            sqv += __shfl_xor_sync(0xffffffffu, sqv, off);
        }
        float mu = smv * (1.f / 128.f);
        float inv = rsqrtf(sqv * (1.f / 128.f) - mu * mu + 1e-5f);
        float g[4]; float vv[4] = {vq.x, vq.y, vq.z, vq.w};
        #pragma unroll
        for (int j = 0; j < 4; j++) {
            int o = lane * 4 + j;
            float u = (vv[j] - mu) * inv * ln_w[o] + ln_b[o];
            g[j] = 0.5f * u * (1.f + erff(u * 0.70710678118654752f));
        }
        float s4 = g[0] + g[1] + g[2] + g[3];
        float q4 = g[0] * g[0] + g[1] * g[1] + g[2] * g[2] + g[3] * g[3];
        float s8 = s4 + __shfl_xor_sync(0xffffffffu, s4, 1);
        float q8 = q4 + __shfl_xor_sync(0xffffffffu, q4, 1);
        float mu2 = s8 * 0.125f;
        float inv2 = rsqrtf(q8 * 0.125f - mu2 * mu2 + 1e-5f);
        #pragma unroll
        for (int j = 0; j < 4; j++) {
            int o = lane * 4 + j;
            OB[o * 5 + ss] = (g[j] - mu2) * inv2 * on_w[o] + on_b[o];
        }
    }
    __syncthreads();

    // ---- coalesced store: 4*128 floats
    #pragma unroll
    for (int k = tid; k < 512; k += 256) {
        int o = k >> 2, sw = k & 3;
        out[(((size_t)(b * 128 + o)) << 14) + hrow * 128 + w0 + sw] = OB[o * 5 + sw];
    }
}

// ---------------------------------------------------------------------------
extern "C" void kernel_launch(void* const* d_in, const int* in_sizes, int n_in,
                              void* d_out, int out_size) {
    const float* x        = (const float*)d_in[0];
    const int*   bpos     = (const int*)  d_in[1];
    const float* in_w     = (const float*)d_in[2];
    const float* in_b     = (const float*)d_in[3];
    const float* inconv_w = (const float*)d_in[4];
    const float* inconv_b = (const float*)d_in[5];
    const float* Q        = (const float*)d_in[6];
    const float* k_w      = (const float*)d_in[7];
    const float* k_b      = (const float*)d_in[8];
    const float* mlp_w    = (const float*)d_in[9];
    const float* mlp_b    = (const float*)d_in[10];
    const float* ln_w     = (const float*)d_in[11];
    const float* ln_b     = (const float*)d_in[12];
    const float* on_w     = (const float*)d_in[13];
    const float* on_b     = (const float*)d_in[14];
    float* out = (float*)d_out;

    cudaFuncSetAttribute(ltae_main, cudaFuncAttributeMaxDynamicSharedMemorySize,
                         SMEM_BYTES);

    setup_a<<<64, 256>>>(bpos, in_w, in_b, inconv_w, inconv_b, Q, k_w, mlp_w);
    setup_b<<<64, 256>>>(inconv_w, Q, k_b);
    setup_c<<<64, 256>>>(in_w, in_b);
    ltae_main<<<8192, 256, SMEM_BYTES>>>(x, mlp_b, ln_w, ln_b, on_w, on_b, out);
}

// round 5
// speedup vs baseline: 3.0271x; 1.2219x over previous
#include <cuda_runtime.h>
#include <math.h>

#define TT 20
#define CC 128
#define DM 256
#define NH 16
#define HWP 16384
#define ZROW 132
#define SSTRIDE 2644
#define ASTRIDE 2112

// smem offsets (floats) — 8 samples, tight overlays
#define OFF_Z   0          // raw z; A overlays [0,16896)
#define OFF_PL  16896      // overlays dead z tail after phase 4 (2048)
#define OFF_PH  18944      // (2048)
#define OFF_OB  16896      // reuses PL after phase 6 (1152)
#define OFF_RS  21152      // (2112)
#define OFF_SC  23264      // (2560) COLS overlay pre-phase2; attn in-place after softmax
#define OFF_GS  25824      // (256)
#define OFF_CR  26080      // (128)
#define SMEM_FLOATS 26208
#define SMEM_BYTES (SMEM_FLOATS * 4)

__device__ float g_Rp[NH * CC];
__device__ float g_G[NH * NH];
__device__ float g_bR[NH];
__device__ float g_W4[DM * CC];      // [c4][d][j]
__device__ float g_GWT[NH * DM];     // [g][d]
__device__ float g_bW[DM];
__device__ float g_M4[DM * CC];      // [d4][o][j]
__device__ float g_vconst[2 * TT * DM];
__device__ float g_sconst[2 * TT * NH];

union F2U { float2 f; unsigned long long u; };

__device__ __forceinline__ float2 fma2(float2 a, float2 b, float2 c) {
    F2U ua, ub, uc, ud;
    ua.f = a; ub.f = b; uc.f = c;
    asm("fma.rn.f32x2 %0, %1, %2, %3;"
        : "=l"(ud.u) : "l"(ua.u), "l"(ub.u), "l"(uc.u));
    return ud.f;
}
__device__ __forceinline__ float2 mul2(float2 a, float2 b) {
    F2U ua, ub, ud;
    ua.f = a; ub.f = b;
    asm("mul.rn.f32x2 %0, %1, %2;" : "=l"(ud.u) : "l"(ua.u), "l"(ub.u));
    return ud.f;
}
__device__ __forceinline__ float2 mk2(float a, float b) {
    float2 r; r.x = a; r.y = b; return r;
}

// ---------------------------------------------------------------------------
// ONE setup kernel: work partitioned by blockIdx; qk recomputed per block.
// grid = 120, 256 threads.
__global__ void ltae_setup(const int* __restrict__ bpos,
                           const float* __restrict__ in_w,
                           const float* __restrict__ in_b,
                           const float* __restrict__ inconv_w,
                           const float* __restrict__ inconv_b,
                           const float* __restrict__ Q,
                           const float* __restrict__ k_w,
                           const float* __restrict__ k_b,
                           const float* __restrict__ mlp_w) {
    __shared__ float sqk[NH * DM];
    __shared__ float srow[2 * DM];
    const int tid = threadIdx.x;
    const int blk = blockIdx.x;

    for (int i = tid; i < NH * DM; i += 256) {
        int h = i >> 8, dm = i & 255;
        float acc = 0.f;
        #pragma unroll
        for (int d = 0; d < 4; d++) acc += Q[h * 4 + d] * k_w[(h * 4 + d) * DM + dm];
        sqk[i] = acc;
    }
    __syncthreads();

    if (blk < 16) {
        // R row h -> Rp, G, bR
        const int h = blk;
        if (tid < 128) {
            int c = tid;
            float acc = 0.f;
            for (int dm = 0; dm < DM; dm++)
                acc += sqk[h * DM + dm] * inconv_w[dm * CC + c];
            srow[c] = acc;
            g_Rp[h * CC + c] = in_w[c] * acc;
        }
        __syncthreads();
        if (tid < 16) {
            float acc = 0.f;
            #pragma unroll
            for (int j = 0; j < 8; j++) {
                int c = tid * 8 + j;
                acc += in_w[c] * srow[c];
            }
            g_G[h * 16 + tid] = acc;
        }
        if (tid == 0) {
            float acc = 0.f;
            for (int c = 0; c < CC; c++) acc += in_b[c] * srow[c];
            g_bR[h] = acc;
        }
    } else if (blk < 56) {
        // vconst + sconst for one (b,t)
        const int bt = blk - 16;
        {
            int dm = tid;
            int ii = dm & 15;
            double ex = (double)(2 * (ii / 2)) / 16.0;
            float denom = (float)pow(1000.0, ex);
            float tab = (float)bpos[bt] / denom;
            float pe = (ii & 1) ? cosf(tab) : sinf(tab);
            float vv = inconv_b[dm] + pe;
            g_vconst[bt * DM + dm] = vv;
            srow[dm] = vv;
        }
        __syncthreads();
        if (tid < 16) {
            int h = tid;
            float acc = 0.f;
            #pragma unroll
            for (int d = 0; d < 4; d++) acc += Q[h * 4 + d] * k_b[h * 4 + d];
            for (int dm = 0; dm < DM; dm++) acc += srow[dm] * sqk[h * DM + dm];
            g_sconst[bt * NH + h] = acc;
        }
    } else if (blk < 88) {
        // 8 d rows: W4, GWT, bW
        const int d0 = (blk - 56) * 8;
        for (int k = 0; k < 8; k++) {
            int d = d0 + k;
            if (tid < 128) {
                int c = tid;
                float w = inconv_w[d * CC + c];
                float wp = in_w[c] * w;
                g_W4[(c >> 2) * 1024 + d * 4 + (c & 3)] = wp;
                srow[c] = wp;
                srow[128 + c] = in_b[c] * w;
            }
            __syncthreads();
            if (tid < 16) {
                float acc = 0.f;
                #pragma unroll
                for (int j = 0; j < 8; j++) acc += srow[tid * 8 + j];
                g_GWT[tid * DM + d] = acc;
            }
            if (tid == 0) {
                float acc = 0.f;
                for (int c = 0; c < CC; c++) acc += srow[128 + c];
                g_bW[d] = acc;
            }
            __syncthreads();
        }
    } else {
        // M4 repack: 4 o rows
        const int o0 = (blk - 88) * 4;
        for (int idx = tid; idx < 4 * DM; idx += 256) {
            int oo = o0 + (idx >> 8), dm = idx & 255;
            g_M4[(dm >> 2) * 512 + oo * 4 + (dm & 3)] = mlp_w[oo * DM + dm];
        }
    }
}

// ---------------------------------------------------------------------------
// Main: 512 threads, 8 w positions per block, 2 CTAs/SM.
__global__ void __launch_bounds__(512, 2)
ltae_main(const float* __restrict__ x,
          const float* __restrict__ mlp_b,
          const float* __restrict__ ln_w, const float* __restrict__ ln_b,
          const float* __restrict__ on_w, const float* __restrict__ on_b,
          float* __restrict__ out) {
    extern __shared__ float sm[];
    float* Z    = sm + OFF_Z;
    float* PL   = sm + OFF_PL;
    float* PH   = sm + OFF_PH;
    float* OB   = sm + OFF_OB;
    float* RS   = sm + OFF_RS;
    float* SC   = sm + OFF_SC;   // scores, then attn (in-place transpose)
    float* COLS = sm + OFF_SC;   // overlay, dead before scores written
    float* GS   = sm + OFF_GS;   // (s,g): [0]=inv, [1]=mu*inv
    float* CR   = sm + OFF_CR;

    const int tid = threadIdx.x;
    const int blk = blockIdx.x;
    const int wblk = blk & 15;
    const int hrow = (blk >> 4) & 127;
    const int b = blk >> 11;
    const int w0 = wblk * 8;

    const float* xb = x + (size_t)b * TT * CC * HWP + (size_t)hrow * 128 + w0;

    // stage Rp (vectorized): 512 float4 moves
    {
        int h = tid >> 5, c4 = tid & 31;
        *(float4*)&RS[h * ZROW + c4 * 4] =
            *(const float4*)&g_Rp[h * CC + c4 * 4];
    }

    // ---- Phase 1: gather raw z -> smem, inline column partials (no scale pass)
    const int s = tid & 7;
    const int lane64 = tid >> 3;
    {
        float s0 = 0.f, q0 = 0.f, s1 = 0.f, q1 = 0.f;
        float* zp = Z + s * SSTRIDE;
        #pragma unroll 4
        for (int k = 0; k < 40; k++) {
            int pair = lane64 + (k << 6);
            float val = __ldg(xb + (size_t)pair * HWP + s);
            zp[(pair >> 7) * ZROW + (pair & 127)] = val;
            if (k & 1) { s1 += val; q1 += val * val; }
            else       { s0 += val; q0 += val * val; }
        }
        *(float2*)&COLS[s * 260 + lane64 * 2] = mk2(s0, q0);
        *(float2*)&COLS[s * 260 + (lane64 + 64) * 2] = mk2(s1, q1);
    }
    __syncthreads();

    if (tid < 128) {
        int ss = tid >> 4, g = tid & 15;
        float sum = 0.f, sq = 0.f;
        #pragma unroll
        for (int j = 0; j < 8; j++) {
            float2 p = *(const float2*)&COLS[ss * 260 + (g * 8 + j) * 2];
            sum += p.x; sq += p.y;
        }
        float mu = sum * (1.f / 160.f);
        float var = sq * (1.f / 160.f) - mu * mu;
        float inv = rsqrtf(var + 1e-5f);
        GS[(ss * 16 + g) * 2]     = inv;
        GS[(ss * 16 + g) * 2 + 1] = mu * inv;
    }
    __syncthreads();

    if (tid < 128) {
        int ss = tid >> 4, h = tid & 15;
        float c = g_bR[h];
        #pragma unroll
        for (int g = 0; g < 16; g++)
            c -= GS[(ss * 16 + g) * 2 + 1] * g_G[h * 16 + g];
        CR[ss * 16 + h] = c;
    }
    __syncthreads();

    // ---- Phase 2: scores from RAW z, inv folded per c4-pair
    if (tid < 320) {
        int hq = tid & 3;
        int tmp = tid >> 2;
        int tq = tmp % 10;
        int ss = tmp / 10;
        int t0 = tq * 2;
        const float4* z0 = (const float4*)(Z + ss * SSTRIDE + t0 * ZROW);
        const float4* z1 = (const float4*)(Z + ss * SSTRIDE + (t0 + 1) * ZROW);
        float2 acc[2][4];
        #pragma unroll
        for (int tt = 0; tt < 2; tt++)
            #pragma unroll
            for (int j = 0; j < 4; j++) acc[tt][j] = mk2(0.f, 0.f);
        #pragma unroll 8
        for (int c4 = 0; c4 < 32; c4++) {
            float inv = GS[(ss * 16 + (c4 >> 1)) * 2];
            float2 iv = mk2(inv, inv);
            float4 a0 = z0[c4], a1 = z1[c4];
            float2 a0l = mul2(mk2(a0.x, a0.y), iv);
            float2 a0h = mul2(mk2(a0.z, a0.w), iv);
            float2 a1l = mul2(mk2(a1.x, a1.y), iv);
            float2 a1h = mul2(mk2(a1.z, a1.w), iv);
            #pragma unroll
            for (int j = 0; j < 4; j++) {
                float4 r = *(const float4*)(RS + (hq * 4 + j) * ZROW + c4 * 4);
                acc[0][j] = fma2(a0l, mk2(r.x, r.y), acc[0][j]);
                acc[0][j] = fma2(a0h, mk2(r.z, r.w), acc[0][j]);
                acc[1][j] = fma2(a1l, mk2(r.x, r.y), acc[1][j]);
                acc[1][j] = fma2(a1h, mk2(r.z, r.w), acc[1][j]);
            }
        }
        #pragma unroll
        for (int tt = 0; tt < 2; tt++)
            #pragma unroll
            for (int j = 0; j < 4; j++) {
                int h = hq * 4 + j, t = t0 + tt;
                SC[ss * 320 + h * 20 + t] =
                    (acc[tt][j].x + acc[tt][j].y + CR[ss * 16 + h]
                     + g_sconst[(b * TT + t) * NH + h]) * 0.5f;
            }
    }
    __syncthreads();

    // ---- Phase 3: softmax with in-place transpose SC -> attn[s][t][h]
    {
        float att[TT];
        int ss = tid >> 4, h = tid & 15;
        if (tid < 128) {
            const float* sp = SC + ss * 320 + h * 20;
            float m = -1e30f;
            #pragma unroll
            for (int t = 0; t < TT; t++) m = fmaxf(m, sp[t]);
            float sumv = 0.f;
            #pragma unroll
            for (int t = 0; t < TT; t++) { att[t] = expf(sp[t] - m); sumv += att[t]; }
            float r = 1.f / sumv;
            #pragma unroll
            for (int t = 0; t < TT; t++) att[t] *= r;
        }
        __syncthreads();
        if (tid < 128) {
            #pragma unroll
            for (int t = 0; t < TT; t++) SC[ss * 320 + t * 16 + h] = att[t];
        }
    }
    __syncthreads();

    // ---- Phase 4: A[s,h,c] = inv_g * sum_t attn * z_raw, overlay into Z
    {
        const int ss4 = tid >> 6;         // sample 0..7
        const int cl = tid & 63;          // c pair
        float2 acc[8][2];
        #pragma unroll
        for (int hp = 0; hp < 8; hp++) {
            acc[hp][0] = mk2(0.f, 0.f);
            acc[hp][1] = mk2(0.f, 0.f);
        }
        const float* zp = Z + ss4 * SSTRIDE + cl * 2;
        const float* ap = SC + ss4 * 320;
        #pragma unroll 4
        for (int t = 0; t < TT; t++) {
            float2 zz = *(const float2*)(zp + t * ZROW);
            float2 zx = mk2(zz.x, zz.x), zy = mk2(zz.y, zz.y);
            const float2* aq = (const float2*)(ap + t * 16);
            #pragma unroll
            for (int hp = 0; hp < 8; hp++) {
                float2 ah = aq[hp];
                acc[hp][0] = fma2(ah, zx, acc[hp][0]);
                acc[hp][1] = fma2(ah, zy, acc[hp][1]);
            }
        }
        float inv = GS[(ss4 * 16 + (cl >> 2)) * 2];
        float2 iv = mk2(inv, inv);
        __syncthreads();                  // all raw-z reads complete
        #pragma unroll
        for (int hp = 0; hp < 8; hp++) {
            float2 a0 = mul2(acc[hp][0], iv);
            float2 a1 = mul2(acc[hp][1], iv);
            *(float2*)(Z + ss4 * ASTRIDE + (2 * hp) * ZROW + cl * 2)     = mk2(a0.x, a1.x);
            *(float2*)(Z + ss4 * ASTRIDE + (2 * hp + 1) * ZROW + cl * 2) = mk2(a0.y, a1.y);
        }
    }
    __syncthreads();

    // ---- Phase 5: pooled; thread owns (d, sample-half)
    {
        const int d = tid & 255;
        const int sh = tid >> 8;          // 0..1 -> samples sh*4..sh*4+3
        const int h = d >> 4;
        float2 acc2[4];
        #pragma unroll
        for (int j = 0; j < 4; j++) acc2[j] = mk2(0.f, 0.f);
        #pragma unroll 4
        for (int c4 = 0; c4 < 32; c4++) {
            float4 w = __ldg((const float4*)(g_W4 + c4 * 1024 + d * 4));
            float2 wl = mk2(w.x, w.y), wh = mk2(w.z, w.w);
            #pragma unroll
            for (int j = 0; j < 4; j++) {
                float4 a = *(const float4*)(Z + (sh * 4 + j) * ASTRIDE + h * ZROW + c4 * 4);
                acc2[j] = fma2(mk2(a.x, a.y), wl, acc2[j]);
                acc2[j] = fma2(mk2(a.z, a.w), wh, acc2[j]);
            }
        }
        float p[4];
        float bw = __ldg(g_bW + d);
        #pragma unroll
        for (int j = 0; j < 4; j++) p[j] = acc2[j].x + acc2[j].y + bw;
        #pragma unroll
        for (int g = 0; g < 16; g++) {
            float gw = __ldg(g_GWT + g * 256 + d);
            #pragma unroll
            for (int j = 0; j < 4; j++)
                p[j] -= GS[((sh * 4 + j) * 16 + g) * 2 + 1] * gw;
        }
        const float* vc = g_vconst + b * TT * DM + d;
        #pragma unroll 4
        for (int t = 0; t < TT; t++) {
            float vv = __ldg(vc + t * DM);
            #pragma unroll
            for (int j = 0; j < 4; j++)
                p[j] += SC[(sh * 4 + j) * 320 + t * 16 + h] * vv;
        }
        #pragma unroll
        for (int j = 0; j < 4; j++) PL[(sh * 4 + j) * 256 + d] = p[j];
    }
    __syncthreads();

    // ---- Phase 6: MLP; thread owns (o, d-half, sample-half)
    {
        const int o = tid & 127;
        const int dh = (tid >> 7) & 1;
        const int sh = tid >> 8;
        float2 acc2[4];
        #pragma unroll
        for (int j = 0; j < 4; j++) acc2[j] = mk2(0.f, 0.f);
        const int d4base = dh * 32;
        #pragma unroll 4
        for (int k = 0; k < 32; k++) {
            int d4 = d4base + k;
            float4 w = __ldg((const float4*)(g_M4 + d4 * 512 + o * 4));
            float2 wl = mk2(w.x, w.y), wh = mk2(w.z, w.w);
            #pragma unroll
            for (int j = 0; j < 4; j++) {
                float4 pq = *(const float4*)(PL + (sh * 4 + j) * 256 + d4 * 4);
                acc2[j] = fma2(mk2(pq.x, pq.y), wl, acc2[j]);
                acc2[j] = fma2(mk2(pq.z, pq.w), wh, acc2[j]);
            }
        }
        #pragma unroll
        for (int j = 0; j < 4; j++)
            PH[dh * 1024 + (sh * 4 + j) * 128 + o] = acc2[j].x + acc2[j].y;
    }
    __syncthreads();

    // ---- Phase 7: combine + LN + GELU + GN + transpose (256 threads)
    if (tid < 256) {
        int ss = tid >> 5, lane = tid & 31;
        float4 a0 = *(const float4*)(PH + ss * 128 + lane * 4);
        float4 a1 = *(const float4*)(PH + 1024 + ss * 128 + lane * 4);
        float4 bb = __ldg((const float4*)(mlp_b + lane * 4));
        float4 vq;
        vq.x = a0.x + a1.x + bb.x;
        vq.y = a0.y + a1.y + bb.y;
        vq.z = a0.z + a1.z + bb.z;
        vq.w = a0.w + a1.w + bb.w;
        float smv = vq.x + vq.y + vq.z + vq.w;
        float sqv = vq.x * vq.x + vq.y * vq.y + vq.z * vq.z + vq.w * vq.w;
        #pragma unroll
        for (int off = 16; off; off >>= 1) {
            smv += __shfl_xor_sync(0xffffffffu, smv, off);
            sqv += __shfl_xor_sync(0xffffffffu, sqv, off);
        }
        float mu = smv * (1.f / 128.f);
        float inv = rsqrtf(sqv * (1.f / 128.f) - mu * mu + 1e-5f);
        float g[4]; float vv[4] = {vq.x, vq.y, vq.z, vq.w};
        #pragma unroll
        for (int j = 0; j < 4; j++) {
            int o = lane * 4 + j;
            float u = (vv[j] - mu) * inv * ln_w[o] + ln_b[o];
            g[j] = 0.5f * u * (1.f + erff(u * 0.70710678118654752f));
        }
        float s4 = g[0] + g[1] + g[2] + g[3];
        float q4 = g[0] * g[0] + g[1] * g[1] + g[2] * g[2] + g[3] * g[3];
        float s8 = s4 + __shfl_xor_sync(0xffffffffu, s4, 1);
        float q8 = q4 + __shfl_xor_sync(0xffffffffu, q4, 1);
        float mu2 = s8 * 0.125f;
        float inv2 = rsqrtf(q8 * 0.125f - mu2 * mu2 + 1e-5f);
        #pragma unroll
        for (int j = 0; j < 4; j++) {
            int o = lane * 4 + j;
            OB[o * 9 + ss] = (g[j] - mu2) * inv2 * on_w[o] + on_b[o];
        }
    }
    __syncthreads();

    // ---- coalesced store: 8*128 floats
    #pragma unroll
    for (int k = tid; k < 1024; k += 512) {
        int o = k >> 3, sw = k & 7;
        out[(((size_t)(b * 128 + o)) << 14) + hrow * 128 + w0 + sw] = OB[o * 9 + sw];
    }
}

// ---------------------------------------------------------------------------
extern "C" void kernel_launch(void* const* d_in, const int* in_sizes, int n_in,
                              void* d_out, int out_size) {
    const float* x        = (const float*)d_in[0];
    const int*   bpos     = (const int*)  d_in[1];
    const float* in_w     = (const float*)d_in[2];
    const float* in_b     = (const float*)d_in[3];
    const float* inconv_w = (const float*)d_in[4];
    const float* inconv_b = (const float*)d_in[5];
    const float* Q        = (const float*)d_in[6];
    const float* k_w      = (const float*)d_in[7];
    const float* k_b      = (const float*)d_in[8];
    const float* mlp_w    = (const float*)d_in[9];
    const float* mlp_b    = (const float*)d_in[10];
    const float* ln_w     = (const float*)d_in[11];
    const float* ln_b     = (const float*)d_in[12];
    const float* on_w     = (const float*)d_in[13];
    const float* on_b     = (const float*)d_in[14];
    float* out = (float*)d_out;

    cudaFuncSetAttribute(ltae_main, cudaFuncAttributeMaxDynamicSharedMemorySize,
                         SMEM_BYTES);

    ltae_setup<<<120, 256>>>(bpos, in_w, in_b, inconv_w, inconv_b, Q, k_w, k_b,
                             mlp_w);
    ltae_main<<<4096, 512, SMEM_BYTES>>>(x, mlp_b, ln_w, ln_b, on_w, on_b, out);
}

// round 6
// speedup vs baseline: 3.2562x; 1.0757x over previous
#include <cuda_runtime.h>
#include <math.h>

#define TT 20
#define CC 128
#define DM 256
#define NH 16
#define HWP 16384
#define ZROW 132
#define SSTRIDE 2644
#define ASTRIDE 2112

// smem offsets (floats) — 8 samples, tight overlays
#define OFF_Z   0          // raw z; A overlays [0,16896)
#define OFF_PL  16896
#define OFF_PH  18944
#define OFF_OB  16896      // reuses PL after phase 6
#define OFF_RS  21152
#define OFF_SC  23264      // scores -> attn (in-place transpose); COLS overlay
#define OFF_GS  25824
#define OFF_CR  26080
#define SMEM_FLOATS 26208
#define SMEM_BYTES (SMEM_FLOATS * 4)

__device__ float g_Rp[NH * CC];
__device__ float g_G[NH * NH];
__device__ float g_bR[NH];
__device__ float g_W4[DM * CC];      // [c4][d][j]
__device__ float g_GWT[NH * DM];     // [g][d]
__device__ float g_bW[DM];
__device__ float g_M4[DM * CC];      // [d4][o][j]
__device__ float g_vconst[2 * TT * DM];
__device__ float g_sconst[2 * TT * NH];

union F2U { float2 f; unsigned long long u; };

__device__ __forceinline__ float2 fma2(float2 a, float2 b, float2 c) {
    F2U ua, ub, uc, ud;
    ua.f = a; ub.f = b; uc.f = c;
    asm("fma.rn.f32x2 %0, %1, %2, %3;"
        : "=l"(ud.u) : "l"(ua.u), "l"(ub.u), "l"(uc.u));
    return ud.f;
}
__device__ __forceinline__ float2 mul2(float2 a, float2 b) {
    F2U ua, ub, ud;
    ua.f = a; ub.f = b;
    asm("mul.rn.f32x2 %0, %1, %2;" : "=l"(ud.u) : "l"(ua.u), "l"(ub.u));
    return ud.f;
}
__device__ __forceinline__ float2 mk2(float a, float b) {
    float2 r; r.x = a; r.y = b; return r;
}

// ---------------------------------------------------------------------------
// Setup (grid 120, 256 thr) — unchanged from R5
__global__ void ltae_setup(const int* __restrict__ bpos,
                           const float* __restrict__ in_w,
                           const float* __restrict__ in_b,
                           const float* __restrict__ inconv_w,
                           const float* __restrict__ inconv_b,
                           const float* __restrict__ Q,
                           const float* __restrict__ k_w,
                           const float* __restrict__ k_b,
                           const float* __restrict__ mlp_w) {
    __shared__ float sqk[NH * DM];
    __shared__ float srow[2 * DM];
    const int tid = threadIdx.x;
    const int blk = blockIdx.x;

    for (int i = tid; i < NH * DM; i += 256) {
        int h = i >> 8, dm = i & 255;
        float acc = 0.f;
        #pragma unroll
        for (int d = 0; d < 4; d++) acc += Q[h * 4 + d] * k_w[(h * 4 + d) * DM + dm];
        sqk[i] = acc;
    }
    __syncthreads();

    if (blk < 16) {
        const int h = blk;
        if (tid < 128) {
            int c = tid;
            float acc = 0.f;
            for (int dm = 0; dm < DM; dm++)
                acc += sqk[h * DM + dm] * inconv_w[dm * CC + c];
            srow[c] = acc;
            g_Rp[h * CC + c] = in_w[c] * acc;
        }
        __syncthreads();
        if (tid < 16) {
            float acc = 0.f;
            #pragma unroll
            for (int j = 0; j < 8; j++) {
                int c = tid * 8 + j;
                acc += in_w[c] * srow[c];
            }
            g_G[h * 16 + tid] = acc;
        }
        if (tid == 0) {
            float acc = 0.f;
            for (int c = 0; c < CC; c++) acc += in_b[c] * srow[c];
            g_bR[h] = acc;
        }
    } else if (blk < 56) {
        const int bt = blk - 16;
        {
            int dm = tid;
            int ii = dm & 15;
            double ex = (double)(2 * (ii / 2)) / 16.0;
            float denom = (float)pow(1000.0, ex);
            float tab = (float)bpos[bt] / denom;
            float pe = (ii & 1) ? cosf(tab) : sinf(tab);
            float vv = inconv_b[dm] + pe;
            g_vconst[bt * DM + dm] = vv;
            srow[dm] = vv;
        }
        __syncthreads();
        if (tid < 16) {
            int h = tid;
            float acc = 0.f;
            #pragma unroll
            for (int d = 0; d < 4; d++) acc += Q[h * 4 + d] * k_b[h * 4 + d];
            for (int dm = 0; dm < DM; dm++) acc += srow[dm] * sqk[h * DM + dm];
            g_sconst[bt * NH + h] = acc;
        }
    } else if (blk < 88) {
        const int d0 = (blk - 56) * 8;
        for (int k = 0; k < 8; k++) {
            int d = d0 + k;
            if (tid < 128) {
                int c = tid;
                float w = inconv_w[d * CC + c];
                float wp = in_w[c] * w;
                g_W4[(c >> 2) * 1024 + d * 4 + (c & 3)] = wp;
                srow[c] = wp;
                srow[128 + c] = in_b[c] * w;
            }
            __syncthreads();
            if (tid < 16) {
                float acc = 0.f;
                #pragma unroll
                for (int j = 0; j < 8; j++) acc += srow[tid * 8 + j];
                g_GWT[tid * DM + d] = acc;
            }
            if (tid == 0) {
                float acc = 0.f;
                for (int c = 0; c < CC; c++) acc += srow[128 + c];
                g_bW[d] = acc;
            }
            __syncthreads();
        }
    } else {
        const int o0 = (blk - 88) * 4;
        for (int idx = tid; idx < 4 * DM; idx += 256) {
            int oo = o0 + (idx >> 8), dm = idx & 255;
            g_M4[(dm >> 2) * 512 + oo * 4 + (dm & 3)] = mlp_w[oo * DM + dm];
        }
    }
}

// ---------------------------------------------------------------------------
// Main: 512 threads, 8 w positions per block, 2 CTAs/SM.
__global__ void __launch_bounds__(512, 2)
ltae_main(const float* __restrict__ x,
          const float* __restrict__ mlp_b,
          const float* __restrict__ ln_w, const float* __restrict__ ln_b,
          const float* __restrict__ on_w, const float* __restrict__ on_b,
          float* __restrict__ out) {
    extern __shared__ float sm[];
    float* Z    = sm + OFF_Z;
    float* PL   = sm + OFF_PL;
    float* PH   = sm + OFF_PH;
    float* OB   = sm + OFF_OB;
    float* RS   = sm + OFF_RS;
    float* SC   = sm + OFF_SC;
    float* COLS = sm + OFF_SC;
    float* GS   = sm + OFF_GS;
    float* CR   = sm + OFF_CR;

    const int tid = threadIdx.x;
    const int blk = blockIdx.x;
    const int wblk = blk & 15;
    const int hrow = (blk >> 4) & 127;
    const int b = blk >> 11;
    const int w0 = wblk * 8;

    const float* xb = x + (size_t)b * TT * CC * HWP + (size_t)hrow * 128 + w0;

    // stage Rp (one float4 per thread)
    {
        int h = tid >> 5, c4 = tid & 31;
        *(float4*)&RS[h * ZROW + c4 * 4] =
            *(const float4*)&g_Rp[h * CC + c4 * 4];
    }

    // ---- Phase 1: gather raw z -> smem, inline column partials
    const int s = tid & 7;
    const int lane64 = tid >> 3;
    {
        float s0 = 0.f, q0 = 0.f, s1 = 0.f, q1 = 0.f;
        float* zp = Z + s * SSTRIDE;
        #pragma unroll 4
        for (int k = 0; k < 40; k++) {
            int pair = lane64 + (k << 6);
            float val = __ldg(xb + (size_t)pair * HWP + s);
            zp[(pair >> 7) * ZROW + (pair & 127)] = val;
            if (k & 1) { s1 += val; q1 += val * val; }
            else       { s0 += val; q0 += val * val; }
        }
        *(float2*)&COLS[s * 260 + lane64 * 2] = mk2(s0, q0);
        *(float2*)&COLS[s * 260 + (lane64 + 64) * 2] = mk2(s1, q1);
    }
    __syncthreads();

    if (tid < 128) {
        int ss = tid >> 4, g = tid & 15;
        float sum = 0.f, sq = 0.f;
        #pragma unroll
        for (int j = 0; j < 8; j++) {
            float2 p = *(const float2*)&COLS[ss * 260 + (g * 8 + j) * 2];
            sum += p.x; sq += p.y;
        }
        float mu = sum * (1.f / 160.f);
        float var = sq * (1.f / 160.f) - mu * mu;
        float inv = rsqrtf(var + 1e-5f);
        GS[(ss * 16 + g) * 2]     = inv;
        GS[(ss * 16 + g) * 2 + 1] = mu * inv;
    }
    __syncthreads();

    if (tid < 128) {
        int ss = tid >> 4, h = tid & 15;
        float c = g_bR[h];
        #pragma unroll
        for (int g = 0; g < 16; g++)
            c -= GS[(ss * 16 + g) * 2 + 1] * g_G[h * 16 + g];
        CR[ss * 16 + h] = c;
    }
    __syncthreads();

    // ---- Phase 2: scores from RAW z, 4t x 4h register tile, inv folded
    if (tid < 160) {
        const int hq = tid & 3;
        const int tmp = tid >> 2;      // 0..39
        const int tq = tmp % 5;
        const int ss = tmp / 5;
        const int t0 = tq * 4;
        const float* zb = Z + ss * SSTRIDE + t0 * ZROW;
        const float* rb = RS + hq * 4 * ZROW;
        float2 acc[4][4];
        #pragma unroll
        for (int tt = 0; tt < 4; tt++)
            #pragma unroll
            for (int j = 0; j < 4; j++) acc[tt][j] = mk2(0.f, 0.f);
        #pragma unroll 4
        for (int c4 = 0; c4 < 32; c4++) {
            float inv = GS[(ss * 16 + (c4 >> 1)) * 2];
            float2 iv = mk2(inv, inv);
            float2 al[4], ah[4];
            #pragma unroll
            for (int tt = 0; tt < 4; tt++) {
                float4 a = *(const float4*)(zb + tt * ZROW + c4 * 4);
                al[tt] = mul2(mk2(a.x, a.y), iv);
                ah[tt] = mul2(mk2(a.z, a.w), iv);
            }
            #pragma unroll
            for (int j = 0; j < 4; j++) {
                float4 r = *(const float4*)(rb + j * ZROW + c4 * 4);
                float2 rl = mk2(r.x, r.y), rh = mk2(r.z, r.w);
                #pragma unroll
                for (int tt = 0; tt < 4; tt++) {
                    acc[tt][j] = fma2(al[tt], rl, acc[tt][j]);
                    acc[tt][j] = fma2(ah[tt], rh, acc[tt][j]);
                }
            }
        }
        #pragma unroll
        for (int tt = 0; tt < 4; tt++)
            #pragma unroll
            for (int j = 0; j < 4; j++) {
                int h = hq * 4 + j, t = t0 + tt;
                SC[ss * 320 + h * 20 + t] =
                    (acc[tt][j].x + acc[tt][j].y + CR[ss * 16 + h]
                     + g_sconst[(b * TT + t) * NH + h]) * 0.5f;
            }
    }
    __syncthreads();

    // ---- Phase 3: softmax with in-place transpose SC -> attn[s][t][h]
    {
        float att[TT];
        int ss = tid >> 4, h = tid & 15;
        if (tid < 128) {
            const float* sp = SC + ss * 320 + h * 20;
            float m = -1e30f;
            #pragma unroll
            for (int t = 0; t < TT; t++) m = fmaxf(m, sp[t]);
            float sumv = 0.f;
            #pragma unroll
            for (int t = 0; t < TT; t++) { att[t] = expf(sp[t] - m); sumv += att[t]; }
            float r = 1.f / sumv;
            #pragma unroll
            for (int t = 0; t < TT; t++) att[t] *= r;
        }
        __syncthreads();
        if (tid < 128) {
            #pragma unroll
            for (int t = 0; t < TT; t++) SC[ss * 320 + t * 16 + h] = att[t];
        }
    }
    __syncthreads();

    // ---- Phase 4: A[s,h,c] = inv_g * sum_t attn * z_raw, overlay into Z
    {
        const int ss4 = tid >> 6;
        const int cl = tid & 63;
        float2 acc[8][2];
        #pragma unroll
        for (int hp = 0; hp < 8; hp++) {
            acc[hp][0] = mk2(0.f, 0.f);
            acc[hp][1] = mk2(0.f, 0.f);
        }
        const float* zp = Z + ss4 * SSTRIDE + cl * 2;
        const float* ap = SC + ss4 * 320;
        #pragma unroll 4
        for (int t = 0; t < TT; t++) {
            float2 zz = *(const float2*)(zp + t * ZROW);
            float2 zx = mk2(zz.x, zz.x), zy = mk2(zz.y, zz.y);
            const float4* aq4 = (const float4*)(ap + t * 16);
            #pragma unroll
            for (int q = 0; q < 4; q++) {
                float4 A4 = aq4[q];
                float2 a01 = mk2(A4.x, A4.y);   // heads 4q, 4q+1
                float2 a23 = mk2(A4.z, A4.w);   // heads 4q+2, 4q+3
                acc[2 * q][0]     = fma2(a01, zx, acc[2 * q][0]);
                acc[2 * q][1]     = fma2(a01, zy, acc[2 * q][1]);
                acc[2 * q + 1][0] = fma2(a23, zx, acc[2 * q + 1][0]);
                acc[2 * q + 1][1] = fma2(a23, zy, acc[2 * q + 1][1]);
            }
        }
        float inv = GS[(ss4 * 16 + (cl >> 2)) * 2];
        float2 iv = mk2(inv, inv);
        __syncthreads();
        #pragma unroll
        for (int hp = 0; hp < 8; hp++) {
            float2 a0 = mul2(acc[hp][0], iv);
            float2 a1 = mul2(acc[hp][1], iv);
            *(float2*)(Z + ss4 * ASTRIDE + (2 * hp) * ZROW + cl * 2)     = mk2(a0.x, a1.x);
            *(float2*)(Z + ss4 * ASTRIDE + (2 * hp + 1) * ZROW + cl * 2) = mk2(a0.y, a1.y);
        }
    }
    __syncthreads();

    // ---- Phase 5: pooled; 256 threads own d, single pass over 8 samples
    if (tid < 256) {
        const int d = tid;
        const int h = d >> 4;
        float2 acc2[8];
        #pragma unroll
        for (int j = 0; j < 8; j++) acc2[j] = mk2(0.f, 0.f);
        #pragma unroll 4
        for (int c4 = 0; c4 < 32; c4++) {
            float4 w = __ldg((const float4*)(g_W4 + c4 * 1024 + d * 4));
            float2 wl = mk2(w.x, w.y), wh = mk2(w.z, w.w);
            #pragma unroll
            for (int j = 0; j < 8; j++) {
                float4 a = *(const float4*)(Z + j * ASTRIDE + h * ZROW + c4 * 4);
                acc2[j] = fma2(mk2(a.x, a.y), wl, acc2[j]);
                acc2[j] = fma2(mk2(a.z, a.w), wh, acc2[j]);
            }
        }
        float p[8];
        float bw = __ldg(g_bW + d);
        #pragma unroll
        for (int j = 0; j < 8; j++) p[j] = acc2[j].x + acc2[j].y + bw;
        #pragma unroll
        for (int g = 0; g < 16; g++) {
            float gw = __ldg(g_GWT + g * 256 + d);
            #pragma unroll
            for (int j = 0; j < 8; j++)
                p[j] -= GS[(j * 16 + g) * 2 + 1] * gw;
        }
        const float* vc = g_vconst + b * TT * DM + d;
        #pragma unroll 4
        for (int t = 0; t < TT; t++) {
            float vv = __ldg(vc + t * DM);
            #pragma unroll
            for (int j = 0; j < 8; j++)
                p[j] += SC[j * 320 + t * 16 + h] * vv;
        }
        #pragma unroll
        for (int j = 0; j < 8; j++) PL[j * 256 + d] = p[j];
    }
    __syncthreads();

    // ---- Phase 6: MLP; 256 threads own (o, d-half), single pass, 8 samples
    if (tid < 256) {
        const int o = tid & 127;
        const int dh = tid >> 7;
        float2 acc2[8];
        #pragma unroll
        for (int j = 0; j < 8; j++) acc2[j] = mk2(0.f, 0.f);
        const int d4base = dh * 32;
        #pragma unroll 4
        for (int k = 0; k < 32; k++) {
            int d4 = d4base + k;
            float4 w = __ldg((const float4*)(g_M4 + d4 * 512 + o * 4));
            float2 wl = mk2(w.x, w.y), wh = mk2(w.z, w.w);
            #pragma unroll
            for (int j = 0; j < 8; j++) {
                float4 pq = *(const float4*)(PL + j * 256 + d4 * 4);
                acc2[j] = fma2(mk2(pq.x, pq.y), wl, acc2[j]);
                acc2[j] = fma2(mk2(pq.z, pq.w), wh, acc2[j]);
            }
        }
        #pragma unroll
        for (int j = 0; j < 8; j++)
            PH[dh * 1024 + j * 128 + o] = acc2[j].x + acc2[j].y;
    }
    __syncthreads();

    // ---- Phase 7: combine + LN + GELU + GN + transpose (256 threads)
    if (tid < 256) {
        int ss = tid >> 5, lane = tid & 31;
        float4 a0 = *(const float4*)(PH + ss * 128 + lane * 4);
        float4 a1 = *(const float4*)(PH + 1024 + ss * 128 + lane * 4);
        float4 bb = __ldg((const float4*)(mlp_b + lane * 4));
        float4 vq;
        vq.x = a0.x + a1.x + bb.x;
        vq.y = a0.y + a1.y + bb.y;
        vq.z = a0.z + a1.z + bb.z;
        vq.w = a0.w + a1.w + bb.w;
        float smv = vq.x + vq.y + vq.z + vq.w;
        float sqv = vq.x * vq.x + vq.y * vq.y + vq.z * vq.z + vq.w * vq.w;
        #pragma unroll
        for (int off = 16; off; off >>= 1) {
            smv += __shfl_xor_sync(0xffffffffu, smv, off);
            sqv += __shfl_xor_sync(0xffffffffu, sqv, off);
        }
        float mu = smv * (1.f / 128.f);
        float inv = rsqrtf(sqv * (1.f / 128.f) - mu * mu + 1e-5f);
        float g[4]; float vv[4] = {vq.x, vq.y, vq.z, vq.w};
        #pragma unroll
        for (int j = 0; j < 4; j++) {
            int o = lane * 4 + j;
            float u = (vv[j] - mu) * inv * ln_w[o] + ln_b[o];
            g[j] = 0.5f * u * (1.f + erff(u * 0.70710678118654752f));
        }
        float s4 = g[0] + g[1] + g[2] + g[3];
        float q4 = g[0] * g[0] + g[1] * g[1] + g[2] * g[2] + g[3] * g[3];
        float s8 = s4 + __shfl_xor_sync(0xffffffffu, s4, 1);
        float q8 = q4 + __shfl_xor_sync(0xffffffffu, q4, 1);
        float mu2 = s8 * 0.125f;
        float inv2 = rsqrtf(q8 * 0.125f - mu2 * mu2 + 1e-5f);
        #pragma unroll
        for (int j = 0; j < 4; j++) {
            int o = lane * 4 + j;
            OB[o * 9 + ss] = (g[j] - mu2) * inv2 * on_w[o] + on_b[o];
        }
    }
    __syncthreads();

    // ---- coalesced store: 8*128 floats
    #pragma unroll
    for (int k = tid; k < 1024; k += 512) {
        int o = k >> 3, sw = k & 7;
        out[(((size_t)(b * 128 + o)) << 14) + hrow * 128 + w0 + sw] = OB[o * 9 + sw];
    }
}

// ---------------------------------------------------------------------------
extern "C" void kernel_launch(void* const* d_in, const int* in_sizes, int n_in,
                              void* d_out, int out_size) {
    const float* x        = (const float*)d_in[0];
    const int*   bpos     = (const int*)  d_in[1];
    const float* in_w     = (const float*)d_in[2];
    const float* in_b     = (const float*)d_in[3];
    const float* inconv_w = (const float*)d_in[4];
    const float* inconv_b = (const float*)d_in[5];
    const float* Q        = (const float*)d_in[6];
    const float* k_w      = (const float*)d_in[7];
    const float* k_b      = (const float*)d_in[8];
    const float* mlp_w    = (const float*)d_in[9];
    const float* mlp_b    = (const float*)d_in[10];
    const float* ln_w     = (const float*)d_in[11];
    const float* ln_b     = (const float*)d_in[12];
    const float* on_w     = (const float*)d_in[13];
    const float* on_b     = (const float*)d_in[14];
    float* out = (float*)d_out;

    cudaFuncSetAttribute(ltae_main, cudaFuncAttributeMaxDynamicSharedMemorySize,
                         SMEM_BYTES);

    ltae_setup<<<120, 256>>>(bpos, in_w, in_b, inconv_w, inconv_b, Q, k_w, k_b,
                             mlp_w);
    ltae_main<<<4096, 512, SMEM_BYTES>>>(x, mlp_b, ln_w, ln_b, on_w, on_b, out);
}